// round 14
// baseline (speedup 1.0000x reference)
#include <cuda_runtime.h>
#include <cuda_fp16.h>
#include <cuda_bf16.h>

#define NUM_U 200000
#define NUM_I 100000
#define DIM   64
#define KTYP  4
#define NKEYS (2*NUM_U + NUM_I + NUM_U)   // A:200K B:200K C:100K D:200K = 700K
#define NB_SCAN ((NKEYS + 1023) / 1024)   // 684
#define E_TOT 8400000

#define BASE_A 0
#define BASE_B (NUM_U)
#define BASE_C (2*NUM_U)
#define BASE_D (2*NUM_U + NUM_I)

#define SI  ((size_t)NUM_I * 32)
#define SI4 ((size_t)NUM_I * 8)
#define SU  ((size_t)NUM_U * 32)

// job sizes
#define GU1 25000
#define GS1 37500
#define T1  (GU1 + GS1)        // 62500  l1 blocks
#define GU2 6250
#define T2  (GU2 + GS1)        // 43750  l2 blocks
#define NCMB 3125              // comb blocks
// per-group stripe quotas: T2/NCMB=14, T1/NCMB=20, NCMB/NCMB=1
#define Q2 14
#define Q1 20

// ---- scratch (device globals; zero-initialized at module load) ----
__device__ __half2 g_ueh[(size_t)KTYP * NUM_U * 32];
__device__ __half2 g_ieh[(size_t)KTYP * NUM_I * 32];
__device__ __half2 g_ub1a[(size_t)NUM_U * 32];         // ping
__device__ __half2 g_ub1b[(size_t)NUM_U * 32];         // pong
__device__ uint4   g_ib1_v[(size_t)KTYP * NUM_I * 8];  // per-type item L1
__device__ uint4   g_ib2_v[(size_t)KTYP * NUM_I * 8];  // per-type item L2

__device__ float2 g_pack[E_TOT];
__device__ int    g_off[NKEYS + 1];
__device__ int    g_cnt[NKEYS];
__device__ int    g_cur[NKEYS];
__device__ int    g_bsums[NB_SCAN];

// ---------------------------------------------------------------------------
// Build op 1 — prep: fp32->half2 conversion + all histograms.
// ---------------------------------------------------------------------------
__global__ void prep_kernel(
    const float2* __restrict__ uemb, const float2* __restrict__ iemb,
    __half2* __restrict__ ueh, __half2* __restrict__ ieh,
    const int* __restrict__ u2u_r,
    const int* __restrict__ u2i_r0, const int* __restrict__ u2i_r1,
    const int* __restrict__ i2i_c,
    const int* __restrict__ i2u_c0, const int* __restrict__ i2u_c1,
    int* __restrict__ cnt,
    int e_uu, int e_ui0, int e_ui1, int e_ii, int e_iu0, int e_iu1)
{
    const long long UCNT = (long long)KTYP * NUM_U * 32;
    const long long ICNT = (long long)KTYP * NUM_I * 32;
    long long i = (long long)blockIdx.x * blockDim.x + threadIdx.x;

    if (i < UCNT) { float2 f = __ldg(uemb + i); ueh[i] = __floats2half2_rn(f.x, f.y); return; }
    i -= UCNT;
    if (i < ICNT) { float2 f = __ldg(iemb + i); ieh[i] = __floats2half2_rn(f.x, f.y); return; }
    i -= ICNT;
    if (i < e_uu)  { atomicAdd(cnt + BASE_A + __ldg(u2u_r  + i), 1); return; }
    i -= e_uu;
    if (i < e_ui0) { atomicAdd(cnt + BASE_B + __ldg(u2i_r0 + i), 1); return; }
    i -= e_ui0;
    if (i < e_ui1) { atomicAdd(cnt + BASE_B + NUM_U/2 + __ldg(u2i_r1 + i), 1); return; }
    i -= e_ui1;
    if (i < e_ii)  { atomicAdd(cnt + BASE_C + __ldg(i2i_c  + i), 1); return; }
    i -= e_ii;
    if (i < e_iu0) { atomicAdd(cnt + BASE_D + __ldg(i2u_c0 + i), 1); return; }
    i -= e_iu0;
    if (i < e_iu1) { atomicAdd(cnt + BASE_D + __ldg(i2u_c1 + i), 1); return; }
}

// ---------------------------------------------------------------------------
// Build ops 2+3 — two-kernel exclusive scan
// ---------------------------------------------------------------------------
__global__ void __launch_bounds__(1024) scan_reduce(const int* __restrict__ cnt,
                                                    int* __restrict__ bsums)
{
    __shared__ int sh[1024];
    int i = blockIdx.x * 1024 + threadIdx.x;
    sh[threadIdx.x] = (i < NKEYS) ? cnt[i] : 0;
    __syncthreads();
    for (int s = 512; s > 0; s >>= 1) {
        if (threadIdx.x < s) sh[threadIdx.x] += sh[threadIdx.x + s];
        __syncthreads();
    }
    if (threadIdx.x == 0) bsums[blockIdx.x] = sh[0];
}

__global__ void __launch_bounds__(1024) scan_write(const int* __restrict__ cnt,
                                                   const int* __restrict__ bsums,
                                                   int* __restrict__ off,
                                                   int* __restrict__ cur)
{
    __shared__ int sh[1024];
    __shared__ int s_pref;
    int v = (threadIdx.x < blockIdx.x && threadIdx.x < NB_SCAN) ? bsums[threadIdx.x] : 0;
    sh[threadIdx.x] = v;
    __syncthreads();
    for (int s = 512; s > 0; s >>= 1) {
        if (threadIdx.x < s) sh[threadIdx.x] += sh[threadIdx.x + s];
        __syncthreads();
    }
    if (threadIdx.x == 0) s_pref = sh[0];
    __syncthreads();

    int i = blockIdx.x * 1024 + threadIdx.x;
    int c = (i < NKEYS) ? cnt[i] : 0;
    sh[threadIdx.x] = c;
    __syncthreads();
    for (int d = 1; d < 1024; d <<= 1) {
        int t = (threadIdx.x >= d) ? sh[threadIdx.x - d] : 0;
        __syncthreads();
        sh[threadIdx.x] += t;
        __syncthreads();
    }
    int excl = s_pref + sh[threadIdx.x] - c;
    if (i < NKEYS) { off[i] = excl; cur[i] = excl; }
    if (i == NKEYS - 1) off[NKEYS] = excl + c;
}

// ---------------------------------------------------------------------------
// Build op 4 — scatter edges into compact pack; tail zeroes ib1/ib2.
// ---------------------------------------------------------------------------
__global__ void scatter_edges(
    const int* __restrict__ u2u_r, const int* __restrict__ u2u_c, const float* __restrict__ u2u_v,
    const int* __restrict__ u2i_r0, const int* __restrict__ u2i_c0, const float* __restrict__ u2i_v0,
    const int* __restrict__ u2i_r1, const int* __restrict__ u2i_c1, const float* __restrict__ u2i_v1,
    const int* __restrict__ i2i_r, const int* __restrict__ i2i_c, const float* __restrict__ i2i_v,
    const int* __restrict__ i2u_r0, const int* __restrict__ i2u_c0, const float* __restrict__ i2u_v0,
    const int* __restrict__ i2u_r1, const int* __restrict__ i2u_c1, const float* __restrict__ i2u_v1,
    int* __restrict__ cur, float2* __restrict__ pack,
    uint4* __restrict__ zb1, uint4* __restrict__ zb2, long long nzero4,
    int e_uu, int e_ui0, int e_ui1, int e_ii, int e_iu0, int e_iu1)
{
    long long i = (long long)blockIdx.x * blockDim.x + threadIdx.x;
    int key, payload; float val;
    if (i < e_uu) {
        key = BASE_A + __ldg(u2u_r + i); payload = __ldg(u2u_c + i); val = __ldg(u2u_v + i);
    } else if ((i -= e_uu) < e_ui0) {
        key = BASE_B + __ldg(u2i_r0 + i); payload = __ldg(u2i_c0 + i); val = __ldg(u2i_v0 + i);
    } else if ((i -= e_ui0) < e_ui1) {
        key = BASE_B + NUM_U/2 + __ldg(u2i_r1 + i); payload = __ldg(u2i_c1 + i); val = __ldg(u2i_v1 + i);
    } else if ((i -= e_ui1) < e_ii) {
        key = BASE_C + __ldg(i2i_c + i); payload = __ldg(i2i_r + i); val = __ldg(i2i_v + i);
    } else if ((i -= e_ii) < e_iu0) {
        key = BASE_D + __ldg(i2u_c0 + i); payload = __ldg(i2u_r0 + i); val = __ldg(i2u_v0 + i);
    } else if ((i -= e_iu0) < e_iu1) {
        key = BASE_D + __ldg(i2u_c1 + i); payload = __ldg(i2u_r1 + i) + NUM_I/2; val = __ldg(i2u_v1 + i);
    } else {
        i -= e_iu1;
        uint4 z = make_uint4(0, 0, 0, 0);
        if (i < nzero4) zb1[i] = z;
        else if ((i -= nzero4) < nzero4) zb2[i] = z;
        return;
    }
    int pos = atomicAdd(&cur[key], 1);
    pack[pos] = make_float2(__int_as_float(payload), val);
}

// ---------------------------------------------------------------------------
// R9-proven gather segment accumulate (2-deep)
// ---------------------------------------------------------------------------
__device__ __forceinline__ void seg_accum(const float2* __restrict__ pack,
                                          const __half2* __restrict__ src,
                                          int s, int e, int lane,
                                          float& ax, float& ay)
{
    int i = s;
    for (; i + 2 <= e; i += 2) {
        float2 p0 = __ldg(pack + i);
        float2 p1 = __ldg(pack + i + 1);
        float2 v0 = __half22float2(__ldg(src + (size_t)__float_as_int(p0.x) * 32 + lane));
        float2 v1 = __half22float2(__ldg(src + (size_t)__float_as_int(p1.x) * 32 + lane));
        ax = fmaf(p0.y, v0.x, ax); ay = fmaf(p0.y, v0.y, ay);
        ax = fmaf(p1.y, v1.x, ax); ay = fmaf(p1.y, v1.y, ay);
    }
    if (i < e) {
        float2 p = __ldg(pack + i);
        float2 v = __half22float2(__ldg(src + (size_t)__float_as_int(p.x) * 32 + lane));
        ax = fmaf(p.y, v.x, ax); ay = fmaf(p.y, v.y, ay);
    }
}

// ---------------------------------------------------------------------------
// R9-proven scatter-col via red.global.add.v4.f16x2
// ---------------------------------------------------------------------------
__device__ __forceinline__ unsigned pk_h2(__half2 h, float v)
{
    float2 f = __half22float2(h);
    __half2 r = __floats2half2_rn(v * f.x, v * f.y);
    return *reinterpret_cast<unsigned*>(&r);
}

__device__ __forceinline__ void scatter_col(int key,
                                            const int* __restrict__ off,
                                            const float2* __restrict__ pack,
                                            const __half2* __restrict__ src,
                                            __half2* __restrict__ dstbase,
                                            int col, int lane)
{
    int s = __ldg(off + key), e = __ldg(off + key + 1);
    if (s == e) return;
    __half2 rl = __ldg(src + (size_t)col * 32 + lane);
    int j  = lane & 7;
    int ei = lane >> 3;
    __half2 r0 = __shfl_sync(0xffffffffu, rl, 4 * j + 0);
    __half2 r1 = __shfl_sync(0xffffffffu, rl, 4 * j + 1);
    __half2 r2 = __shfl_sync(0xffffffffu, rl, 4 * j + 2);
    __half2 r3 = __shfl_sync(0xffffffffu, rl, 4 * j + 3);
    for (int base = s; base < e; base += 4) {
        int i = base + ei;
        if (i < e) {
            float2 p = __ldg(pack + i);
            int dst = __float_as_int(p.x);
            float v = p.y;
            unsigned q0 = pk_h2(r0, v), q1 = pk_h2(r1, v);
            unsigned q2 = pk_h2(r2, v), q3 = pk_h2(r3, v);
            __half2* ptr = dstbase + (size_t)dst * 32 + 4 * j;
            asm volatile("red.global.add.noftz.v4.f16x2 [%0], {%1,%2,%3,%4};"
                         :: "l"(ptr), "r"(q0), "r"(q1), "r"(q2), "r"(q3)
                         : "memory");
        }
    }
}

// ---------------------------------------------------------------------------
// Job bodies (device functions reused by the phase kernel)
// ---------------------------------------------------------------------------
__device__ __forceinline__ void job_l1(int t,
    const int* __restrict__ off, const float2* __restrict__ pack,
    const __half2* __restrict__ ueh_k, const __half2* __restrict__ ieh_k,
    __half2* __restrict__ ub1, __half2* __restrict__ ib1,
    int warp, int lane)
{
    long long lo = (long long)t * GU1 / T1;
    long long hi = (long long)(t + 1) * GU1 / T1;
    if (hi > lo) {
        int w = (int)lo * 8 + warp;
        float ax = 0.0f, ay = 0.0f;
        seg_accum(pack, ueh_k, __ldg(off + BASE_A + w), __ldg(off + BASE_A + w + 1), lane, ax, ay);
        seg_accum(pack, ieh_k, __ldg(off + BASE_B + w), __ldg(off + BASE_B + w + 1), lane, ax, ay);
        ub1[(size_t)w * 32 + lane] = __floats2half2_rn(ax, ay);
    } else {
        int wg = (t - (int)hi) * 8 + warp;
        if (wg < NUM_I)
            scatter_col(BASE_C + wg, off, pack, ieh_k, ib1, wg, lane);
        else
            scatter_col(BASE_D + (wg - NUM_I), off, pack, ueh_k, ib1, wg - NUM_I, lane);
    }
}

__device__ __forceinline__ void job_l2(int t,
    const int* __restrict__ off, const float2* __restrict__ pack,
    const __half2* __restrict__ ub1, const __half2* __restrict__ ib1,
    __half2* __restrict__ ib2,
    const float* __restrict__ ue0f, const float* __restrict__ W,
    float* __restrict__ out, int out_off,
    float (*Ws)[DIM], int warp, int lane)
{
    long long lo = (long long)t * GU2 / T2;
    long long hi = (long long)(t + 1) * GU2 / T2;
    if (hi > lo) {
        for (int i = threadIdx.x; i < DIM * DIM; i += blockDim.x)
            Ws[i >> 6][i & 63] = W[i];
        __syncthreads();

        for (int w = (int)lo * 8 + warp; w < NUM_U; w += GU2 * 8) {
            float ax = 0.0f, ay = 0.0f;
            seg_accum(pack, ub1, __ldg(off + BASE_A + w), __ldg(off + BASE_A + w + 1), lane, ax, ay);
            seg_accum(pack, ib1, __ldg(off + BASE_B + w), __ldg(off + BASE_B + w + 1), lane, ax, ay);

            const float inv3 = 1.0f / 3.0f;
            float2 f0 = __ldg(reinterpret_cast<const float2*>(ue0f + (size_t)w * DIM) + lane);
            float2 f1 = __half22float2(__ldg(ub1 + (size_t)w * 32 + lane));
            float m0 = (f0.x + f1.x + ax) * inv3;
            float m1 = (f0.y + f1.y + ay) * inv3;

            float acc0 = 0.0f, acc1 = 0.0f;
#pragma unroll
            for (int l = 0; l < 32; l++) {
                float b0 = __shfl_sync(0xffffffffu, m0, l);
                float b1 = __shfl_sync(0xffffffffu, m1, l);
                acc0 += b0 * Ws[2 * l][lane]      + b1 * Ws[2 * l + 1][lane];
                acc1 += b0 * Ws[2 * l][lane + 32] + b1 * Ws[2 * l + 1][lane + 32];
            }
            float* o = out + (size_t)w * (KTYP * DIM) + out_off;
            o[lane]      = fmaxf(acc0, 0.0f);
            o[lane + 32] = fmaxf(acc1, 0.0f);
        }
    } else {
        int wg = (t - (int)hi) * 8 + warp;
        if (wg < NUM_I)
            scatter_col(BASE_C + wg, off, pack, ib1, ib2, wg, lane);
        else
            scatter_col(BASE_D + (wg - NUM_I), off, pack, ub1, ib2, wg - NUM_I, lane);
    }
}

__device__ __forceinline__ void job_comb(int t,
    const float* __restrict__ ie0f,
    const __half2* __restrict__ ib1, const __half2* __restrict__ ib2,
    const float* __restrict__ W, float* __restrict__ out, int out_off,
    float (*Ws)[DIM], int warp, int lane)
{
    for (int i = threadIdx.x; i < DIM * DIM; i += blockDim.x)
        Ws[i >> 6][i & 63] = W[i];
    __syncthreads();

    for (int w = t * 8 + warp; w < NUM_I; w += NCMB * 8) {
        const float inv3 = 1.0f / 3.0f;
        float2 f0 = __ldg(reinterpret_cast<const float2*>(ie0f + (size_t)w * DIM) + lane);
        float2 f1 = __half22float2(__ldg(ib1 + (size_t)w * 32 + lane));
        float2 f2 = __half22float2(__ldg(ib2 + (size_t)w * 32 + lane));
        float m0 = (f0.x + f1.x + f2.x) * inv3;
        float m1 = (f0.y + f1.y + f2.y) * inv3;

        float acc0 = 0.0f, acc1 = 0.0f;
#pragma unroll
        for (int l = 0; l < 32; l++) {
            float b0 = __shfl_sync(0xffffffffu, m0, l);
            float b1 = __shfl_sync(0xffffffffu, m1, l);
            acc0 += b0 * Ws[2 * l][lane]      + b1 * Ws[2 * l + 1][lane];
            acc1 += b0 * Ws[2 * l][lane + 32] + b1 * Ws[2 * l + 1][lane + 32];
        }
        float* o = out + (size_t)w * (KTYP * DIM) + out_off;
        o[lane]      = fmaxf(acc0, 0.0f);
        o[lane + 32] = fmaxf(acc1, 0.0f);
    }
}

// ---------------------------------------------------------------------------
// Phase kernel: stripes of (c2 x l2-job, c1 x l1-job, cc x comb-job) blocks.
// All jobs are mutually independent (different types / double buffers).
// ---------------------------------------------------------------------------
__global__ void __launch_bounds__(256) phase_kernel(
    const int* __restrict__ off, const float2* __restrict__ pack,
    // l2 job (type a)
    const __half2* __restrict__ ub1_rd, const __half2* __restrict__ ib1_a,
    __half2* __restrict__ ib2_a, const float* __restrict__ ue0f_a,
    const float* __restrict__ W_a, float* __restrict__ out_user, int offu,
    // l1 job (type b)
    const __half2* __restrict__ ueh_b, const __half2* __restrict__ ieh_b,
    __half2* __restrict__ ub1_wr, __half2* __restrict__ ib1_b,
    // comb job (type c)
    const float* __restrict__ ie0f_c, const __half2* __restrict__ ib1_c,
    const __half2* __restrict__ ib2_c, const float* __restrict__ W_c,
    float* __restrict__ out_item, int offi,
    int c2, int c1, int cc)
{
    __shared__ float Ws[DIM][DIM];
    int GROUP = c2 + c1 + cc;
    int g = blockIdx.x / GROUP;
    int r = blockIdx.x - g * GROUP;
    int warp = threadIdx.x >> 5, lane = threadIdx.x & 31;

    if (r < c2) {
        job_l2(g * c2 + r, off, pack, ub1_rd, ib1_a, ib2_a,
               ue0f_a, W_a, out_user, offu, Ws, warp, lane);
    } else if (r < c2 + c1) {
        job_l1(g * c1 + (r - c2), off, pack, ueh_b, ieh_b, ub1_wr, ib1_b, warp, lane);
    } else {
        job_comb(g, ie0f_c, ib1_c, ib2_c, W_c, out_item, offi, Ws, warp, lane);
    }
}

// ---------------------------------------------------------------------------
// Final comb kernel (type 3) + cnt re-zero (self-cleaning graph).
// ---------------------------------------------------------------------------
__global__ void __launch_bounds__(256) final_combine(
    const float* __restrict__ ie0f,
    const __half2* __restrict__ ib1, const __half2* __restrict__ ib2,
    const float* __restrict__ W, float* __restrict__ out, int out_off,
    int* __restrict__ cnt_zero)
{
    __shared__ float Ws[DIM][DIM];
    for (long long i = (long long)blockIdx.x * blockDim.x + threadIdx.x;
         i < NKEYS; i += (long long)gridDim.x * blockDim.x)
        cnt_zero[i] = 0;

    int warp = threadIdx.x >> 5, lane = threadIdx.x & 31;
    job_comb(blockIdx.x, ie0f, ib1, ib2, W, out, out_off, Ws, warp, lane);
}

// ---------------------------------------------------------------------------
extern "C" void kernel_launch(void* const* d_in, const int* in_sizes, int n_in,
                              void* d_out, int out_size)
{
    const int* u2u_r  = (const int*)d_in[0];  const int* u2u_c  = (const int*)d_in[1];
    const float* u2u_v = (const float*)d_in[2];
    const int* u2i_r0 = (const int*)d_in[3];  const int* u2i_c0 = (const int*)d_in[4];
    const float* u2i_v0 = (const float*)d_in[5];
    const int* u2i_r1 = (const int*)d_in[6];  const int* u2i_c1 = (const int*)d_in[7];
    const float* u2i_v1 = (const float*)d_in[8];
    const int* i2u_r0 = (const int*)d_in[9];  const int* i2u_c0 = (const int*)d_in[10];
    const float* i2u_v0 = (const float*)d_in[11];
    const int* i2u_r1 = (const int*)d_in[12]; const int* i2u_c1 = (const int*)d_in[13];
    const float* i2u_v1 = (const float*)d_in[14];
    const int* i2i_r  = (const int*)d_in[15]; const int* i2i_c  = (const int*)d_in[16];
    const float* i2i_v = (const float*)d_in[17];
    const float* user_embs = (const float*)d_in[18];
    const float* item_embs = (const float*)d_in[19];
    const float* W_u       = (const float*)d_in[20];
    const float* W_v       = (const float*)d_in[21];

    const int e_uu  = in_sizes[0];
    const int e_ui0 = in_sizes[3], e_ui1 = in_sizes[6];
    const int e_iu0 = in_sizes[9], e_iu1 = in_sizes[12];
    const int e_ii  = in_sizes[15];

    float* out_user = (float*)d_out;
    float* out_item = (float*)d_out + (size_t)NUM_U * (KTYP * DIM);

    __half2 *ueh, *ieh, *ub1a, *ub1b;
    uint4 *ib1v, *ib2v;
    float2 *pack;
    int *off, *cnt, *cur, *bs;
    cudaGetSymbolAddress((void**)&ueh, g_ueh);
    cudaGetSymbolAddress((void**)&ieh, g_ieh);
    cudaGetSymbolAddress((void**)&ub1a, g_ub1a);
    cudaGetSymbolAddress((void**)&ub1b, g_ub1b);
    cudaGetSymbolAddress((void**)&ib1v, g_ib1_v);
    cudaGetSymbolAddress((void**)&ib2v, g_ib2_v);
    cudaGetSymbolAddress((void**)&pack, g_pack);
    cudaGetSymbolAddress((void**)&off, g_off);
    cudaGetSymbolAddress((void**)&cnt, g_cnt);
    cudaGetSymbolAddress((void**)&cur, g_cur);
    cudaGetSymbolAddress((void**)&bs, g_bsums);

    __half2* ib1 = (__half2*)ib1v;
    __half2* ib2 = (__half2*)ib2v;

    // ---- build ----
    {
        long long total = (long long)KTYP * NUM_U * 32 + (long long)KTYP * NUM_I * 32
                        + e_uu + e_ui0 + e_ui1 + e_ii + e_iu0 + e_iu1;
        prep_kernel<<<(int)((total + 255) / 256), 256>>>(
            (const float2*)user_embs, (const float2*)item_embs,
            ueh, ieh, u2u_r, u2i_r0, u2i_r1, i2i_c, i2u_c0, i2u_c1,
            cnt, e_uu, e_ui0, e_ui1, e_ii, e_iu0, e_iu1);
    }
    scan_reduce<<<NB_SCAN, 1024>>>(cnt, bs);
    scan_write<<<NB_SCAN, 1024>>>(cnt, bs, off, cur);
    {
        long long nzero4 = (long long)KTYP * NUM_I * 8;
        long long total = (long long)e_uu + e_ui0 + e_ui1 + e_ii + e_iu0 + e_iu1
                        + 2 * nzero4;
        scatter_edges<<<(int)((total + 255) / 256), 256>>>(
            u2u_r, u2u_c, u2u_v, u2i_r0, u2i_c0, u2i_v0, u2i_r1, u2i_c1, u2i_v1,
            i2i_r, i2i_c, i2i_v, i2u_r0, i2u_c0, i2u_v0, i2u_r1, i2u_c1, i2u_v1,
            cur, pack, ib1v, ib2v, nzero4,
            e_uu, e_ui0, e_ui1, e_ii, e_iu0, e_iu1);
    }

    // ---- pipelined main loop ----
    // l1(k) writes ub1[k&1]; l2(k) reads ub1[k&1]; l1(k+1) runs with l2(k).
    __half2* ubp[2] = { ub1a, ub1b };
    auto UE = [&](int k){ return ueh + (size_t)k * SU; };
    auto IE = [&](int k){ return ieh + (size_t)k * SI; };
    auto UE0 = [&](int k){ return user_embs + (size_t)k * NUM_U * DIM; };
    auto IE0 = [&](int k){ return item_embs + (size_t)k * NUM_I * DIM; };
    auto IB1 = [&](int k){ return ib1 + (size_t)k * SI; };
    auto IB2 = [&](int k){ return ib2 + (size_t)k * SI; };
    auto WU = [&](int k){ return W_u + (size_t)k * DIM * DIM; };
    auto WV = [&](int k){ return W_v + (size_t)k * DIM * DIM; };

    // M0: l1(0)
    phase_kernel<<<NCMB * Q1, 256>>>(off, pack,
        nullptr, nullptr, nullptr, nullptr, nullptr, nullptr, 0,
        UE(0), IE(0), ubp[0], IB1(0),
        nullptr, nullptr, nullptr, nullptr, nullptr, 0,
        0, Q1, 0);

    // M1: l2(0) || l1(1)
    phase_kernel<<<NCMB * (Q2 + Q1), 256>>>(off, pack,
        ubp[0], IB1(0), IB2(0), UE0(0), WU(0), out_user, 0 * DIM,
        UE(1), IE(1), ubp[1], IB1(1),
        nullptr, nullptr, nullptr, nullptr, nullptr, 0,
        Q2, Q1, 0);

    // M2: l2(1) || l1(2) || comb(0)
    phase_kernel<<<NCMB * (Q2 + Q1 + 1), 256>>>(off, pack,
        ubp[1], IB1(1), IB2(1), UE0(1), WU(1), out_user, 1 * DIM,
        UE(2), IE(2), ubp[0], IB1(2),
        IE0(0), IB1(0), IB2(0), WV(0), out_item, 0 * DIM,
        Q2, Q1, 1);

    // M3: l2(2) || l1(3) || comb(1)
    phase_kernel<<<NCMB * (Q2 + Q1 + 1), 256>>>(off, pack,
        ubp[0], IB1(2), IB2(2), UE0(2), WU(2), out_user, 2 * DIM,
        UE(3), IE(3), ubp[1], IB1(3),
        IE0(1), IB1(1), IB2(1), WV(1), out_item, 1 * DIM,
        Q2, Q1, 1);

    // M4: l2(3) || comb(2)
    phase_kernel<<<NCMB * (Q2 + 1), 256>>>(off, pack,
        ubp[1], IB1(3), IB2(3), UE0(3), WU(3), out_user, 3 * DIM,
        nullptr, nullptr, nullptr, nullptr,
        IE0(2), IB1(2), IB2(2), WV(2), out_item, 2 * DIM,
        Q2, 0, 1);

    // M5: comb(3) + cnt re-zero
    final_combine<<<NCMB, 256>>>(IE0(3), IB1(3), IB2(3), WV(3),
                                 out_item, 3 * DIM, cnt);
}

// round 15
// speedup vs baseline: 1.0351x; 1.0351x over previous
#include <cuda_runtime.h>
#include <cuda_fp16.h>
#include <cuda_bf16.h>

#define NUM_U 200000
#define NUM_I 100000
#define DIM   64
#define KTYP  4
#define NKEYS (2*NUM_U + NUM_I + NUM_U)   // A:200K B:200K C:100K D:200K = 700K
#define NB_SCAN ((NKEYS + 1023) / 1024)   // 684
#define E_TOT 8400000

#define BASE_A 0
#define BASE_B (NUM_U)
#define BASE_C (2*NUM_U)
#define BASE_D (2*NUM_U + NUM_I)

#define SI  ((size_t)NUM_I * 32)
#define SI4 ((size_t)NUM_I * 8)

// ---- scratch (device globals; zero-init at load; uint4 => 16B aligned) ----
__device__ uint4   g_ueh_v[(size_t)KTYP * NUM_U * 8];
__device__ uint4   g_ieh_v[(size_t)KTYP * NUM_I * 8];
__device__ uint4   g_ub1_v[(size_t)NUM_U * 8];
__device__ uint4   g_ib1_v[(size_t)KTYP * NUM_I * 8];
__device__ uint4   g_ib2_v[(size_t)KTYP * NUM_I * 8];

__device__ float2 g_pack[E_TOT];
__device__ int    g_off[NKEYS + 1];
__device__ int    g_cnt[NKEYS];      // histogram; re-zeroed at graph tail
__device__ int    g_cur[NKEYS];      // scatter cursors
__device__ int    g_bsums[NB_SCAN];

// ---------------------------------------------------------------------------
// Op 1 — prep: fp32->half2 conversion + all histograms (cnt zero on entry).
// ---------------------------------------------------------------------------
__global__ void prep_kernel(
    const float2* __restrict__ uemb, const float2* __restrict__ iemb,
    __half2* __restrict__ ueh, __half2* __restrict__ ieh,
    const int* __restrict__ u2u_r,
    const int* __restrict__ u2i_r0, const int* __restrict__ u2i_r1,
    const int* __restrict__ i2i_c,
    const int* __restrict__ i2u_c0, const int* __restrict__ i2u_c1,
    int* __restrict__ cnt,
    int e_uu, int e_ui0, int e_ui1, int e_ii, int e_iu0, int e_iu1)
{
    const long long UCNT = (long long)KTYP * NUM_U * 32;
    const long long ICNT = (long long)KTYP * NUM_I * 32;
    long long i = (long long)blockIdx.x * blockDim.x + threadIdx.x;

    if (i < UCNT) { float2 f = __ldg(uemb + i); ueh[i] = __floats2half2_rn(f.x, f.y); return; }
    i -= UCNT;
    if (i < ICNT) { float2 f = __ldg(iemb + i); ieh[i] = __floats2half2_rn(f.x, f.y); return; }
    i -= ICNT;
    if (i < e_uu)  { atomicAdd(cnt + BASE_A + __ldg(u2u_r  + i), 1); return; }
    i -= e_uu;
    if (i < e_ui0) { atomicAdd(cnt + BASE_B + __ldg(u2i_r0 + i), 1); return; }
    i -= e_ui0;
    if (i < e_ui1) { atomicAdd(cnt + BASE_B + NUM_U/2 + __ldg(u2i_r1 + i), 1); return; }
    i -= e_ui1;
    if (i < e_ii)  { atomicAdd(cnt + BASE_C + __ldg(i2i_c  + i), 1); return; }
    i -= e_ii;
    if (i < e_iu0) { atomicAdd(cnt + BASE_D + __ldg(i2u_c0 + i), 1); return; }
    i -= e_iu0;
    if (i < e_iu1) { atomicAdd(cnt + BASE_D + __ldg(i2u_c1 + i), 1); return; }
}

// ---------------------------------------------------------------------------
// Ops 2+3 — two-kernel exclusive scan (writes off + cur)
// ---------------------------------------------------------------------------
__global__ void __launch_bounds__(1024) scan_reduce(const int* __restrict__ cnt,
                                                    int* __restrict__ bsums)
{
    __shared__ int sh[1024];
    int i = blockIdx.x * 1024 + threadIdx.x;
    sh[threadIdx.x] = (i < NKEYS) ? cnt[i] : 0;
    __syncthreads();
    for (int s = 512; s > 0; s >>= 1) {
        if (threadIdx.x < s) sh[threadIdx.x] += sh[threadIdx.x + s];
        __syncthreads();
    }
    if (threadIdx.x == 0) bsums[blockIdx.x] = sh[0];
}

__global__ void __launch_bounds__(1024) scan_write(const int* __restrict__ cnt,
                                                   const int* __restrict__ bsums,
                                                   int* __restrict__ off,
                                                   int* __restrict__ cur)
{
    __shared__ int sh[1024];
    __shared__ int s_pref;
    int v = (threadIdx.x < blockIdx.x && threadIdx.x < NB_SCAN) ? bsums[threadIdx.x] : 0;
    sh[threadIdx.x] = v;
    __syncthreads();
    for (int s = 512; s > 0; s >>= 1) {
        if (threadIdx.x < s) sh[threadIdx.x] += sh[threadIdx.x + s];
        __syncthreads();
    }
    if (threadIdx.x == 0) s_pref = sh[0];
    __syncthreads();

    int i = blockIdx.x * 1024 + threadIdx.x;
    int c = (i < NKEYS) ? cnt[i] : 0;
    sh[threadIdx.x] = c;
    __syncthreads();
    for (int d = 1; d < 1024; d <<= 1) {
        int t = (threadIdx.x >= d) ? sh[threadIdx.x - d] : 0;
        __syncthreads();
        sh[threadIdx.x] += t;
        __syncthreads();
    }
    int excl = s_pref + sh[threadIdx.x] - c;
    if (i < NKEYS) { off[i] = excl; cur[i] = excl; }
    if (i == NKEYS - 1) off[NKEYS] = excl + c;
}

// ---------------------------------------------------------------------------
// Op 4 — scatter edges into compact pack; tail zeroes ib1/ib2.
// ---------------------------------------------------------------------------
__global__ void scatter_edges(
    const int* __restrict__ u2u_r, const int* __restrict__ u2u_c, const float* __restrict__ u2u_v,
    const int* __restrict__ u2i_r0, const int* __restrict__ u2i_c0, const float* __restrict__ u2i_v0,
    const int* __restrict__ u2i_r1, const int* __restrict__ u2i_c1, const float* __restrict__ u2i_v1,
    const int* __restrict__ i2i_r, const int* __restrict__ i2i_c, const float* __restrict__ i2i_v,
    const int* __restrict__ i2u_r0, const int* __restrict__ i2u_c0, const float* __restrict__ i2u_v0,
    const int* __restrict__ i2u_r1, const int* __restrict__ i2u_c1, const float* __restrict__ i2u_v1,
    int* __restrict__ cur, float2* __restrict__ pack,
    uint4* __restrict__ zb1, uint4* __restrict__ zb2, long long nzero4,
    int e_uu, int e_ui0, int e_ui1, int e_ii, int e_iu0, int e_iu1)
{
    long long i = (long long)blockIdx.x * blockDim.x + threadIdx.x;
    int key, payload; float val;
    if (i < e_uu) {
        key = BASE_A + __ldg(u2u_r + i); payload = __ldg(u2u_c + i); val = __ldg(u2u_v + i);
    } else if ((i -= e_uu) < e_ui0) {
        key = BASE_B + __ldg(u2i_r0 + i); payload = __ldg(u2i_c0 + i); val = __ldg(u2i_v0 + i);
    } else if ((i -= e_ui0) < e_ui1) {
        key = BASE_B + NUM_U/2 + __ldg(u2i_r1 + i); payload = __ldg(u2i_c1 + i); val = __ldg(u2i_v1 + i);
    } else if ((i -= e_ui1) < e_ii) {
        key = BASE_C + __ldg(i2i_c + i); payload = __ldg(i2i_r + i); val = __ldg(i2i_v + i);
    } else if ((i -= e_ii) < e_iu0) {
        key = BASE_D + __ldg(i2u_c0 + i); payload = __ldg(i2u_r0 + i); val = __ldg(i2u_v0 + i);
    } else if ((i -= e_iu0) < e_iu1) {
        key = BASE_D + __ldg(i2u_c1 + i); payload = __ldg(i2u_r1 + i) + NUM_I/2; val = __ldg(i2u_v1 + i);
    } else {
        i -= e_iu1;
        uint4 z = make_uint4(0, 0, 0, 0);
        if (i < nzero4) zb1[i] = z;
        else if ((i -= nzero4) < nzero4) zb2[i] = z;
        return;
    }
    int pos = atomicAdd(&cur[key], 1);
    pack[pos] = make_float2(__int_as_float(payload), val);
}

// ---------------------------------------------------------------------------
// R9-proven gather segment accumulate (2-deep pipeline)
// ---------------------------------------------------------------------------
__device__ __forceinline__ void seg_accum(const float2* __restrict__ pack,
                                          const __half2* __restrict__ src,
                                          int s, int e, int lane,
                                          float& ax, float& ay)
{
    int i = s;
    for (; i + 2 <= e; i += 2) {
        float2 p0 = __ldg(pack + i);
        float2 p1 = __ldg(pack + i + 1);
        float2 v0 = __half22float2(__ldg(src + (size_t)__float_as_int(p0.x) * 32 + lane));
        float2 v1 = __half22float2(__ldg(src + (size_t)__float_as_int(p1.x) * 32 + lane));
        ax = fmaf(p0.y, v0.x, ax); ay = fmaf(p0.y, v0.y, ay);
        ax = fmaf(p1.y, v1.x, ax); ay = fmaf(p1.y, v1.y, ay);
    }
    if (i < e) {
        float2 p = __ldg(pack + i);
        float2 v = __half22float2(__ldg(src + (size_t)__float_as_int(p.x) * 32 + lane));
        ax = fmaf(p.y, v.x, ax); ay = fmaf(p.y, v.y, ay);
    }
}

// ---------------------------------------------------------------------------
// R13-lean scatter: uint4 lane-slice preload, hoisted half->float conversion,
// no shfl; per-edge work = 2 fmul + 1 cvt per quarter-slice + 1 red.
// ---------------------------------------------------------------------------
__device__ __forceinline__ unsigned pk_f2(float2 f, float v)
{
    __half2 r = __floats2half2_rn(v * f.x, v * f.y);
    return *reinterpret_cast<unsigned*>(&r);
}

__device__ __forceinline__ void scatter_col(int key,
                                            const int* __restrict__ off,
                                            const float2* __restrict__ pack,
                                            const uint4* __restrict__ src4,
                                            __half2* __restrict__ dstbase,
                                            int col, int lane)
{
    int s = __ldg(off + key), e = __ldg(off + key + 1);
    if (s == e) return;
    int j  = lane & 7;
    int ei = lane >> 3;
    uint4 q = __ldg(src4 + (size_t)col * 8 + j);
    float2 f0 = __half22float2(*reinterpret_cast<__half2*>(&q.x));
    float2 f1 = __half22float2(*reinterpret_cast<__half2*>(&q.y));
    float2 f2 = __half22float2(*reinterpret_cast<__half2*>(&q.z));
    float2 f3 = __half22float2(*reinterpret_cast<__half2*>(&q.w));
    for (int i = s + ei; i < e; i += 4) {
        float2 p = __ldg(pack + i);
        int dst = __float_as_int(p.x);
        float v = p.y;
        unsigned q0 = pk_f2(f0, v), q1 = pk_f2(f1, v);
        unsigned q2 = pk_f2(f2, v), q3 = pk_f2(f3, v);
        __half2* ptr = dstbase + (size_t)dst * 32 + 4 * j;
        asm volatile("red.global.add.noftz.v4.f16x2 [%0], {%1,%2,%3,%4};"
                     :: "l"(ptr), "r"(q0), "r"(q1), "r"(q2), "r"(q3)
                     : "memory");
    }
}

// ---------------------------------------------------------------------------
// Layer 1 hybrid: user gather (R9) + item scatter (lean), role-interleaved.
// ---------------------------------------------------------------------------
#define GU1 25000
#define GS1 37500
#define T1  (GU1 + GS1)

__global__ void __launch_bounds__(256) combined_l1(
    const int* __restrict__ off, const float2* __restrict__ pack,
    const uint4* __restrict__ ueh4_k, const uint4* __restrict__ ieh4_k,
    __half2* __restrict__ ub1, __half2* __restrict__ ib1)
{
    int t = blockIdx.x;
    int warp = threadIdx.x >> 5, lane = threadIdx.x & 31;
    long long lo = (long long)t * GU1 / T1;
    long long hi = (long long)(t + 1) * GU1 / T1;
    if (hi > lo) {
        int w = (int)lo * 8 + warp;
        float ax = 0.0f, ay = 0.0f;
        seg_accum(pack, (const __half2*)ueh4_k, __ldg(off + BASE_A + w), __ldg(off + BASE_A + w + 1), lane, ax, ay);
        seg_accum(pack, (const __half2*)ieh4_k, __ldg(off + BASE_B + w), __ldg(off + BASE_B + w + 1), lane, ax, ay);
        ub1[(size_t)w * 32 + lane] = __floats2half2_rn(ax, ay);
    } else {
        int wg = (t - (int)hi) * 8 + warp;
        if (wg < NUM_I)
            scatter_col(BASE_C + wg, off, pack, ieh4_k, ib1, wg, lane);
        else
            scatter_col(BASE_D + (wg - NUM_I), off, pack, ueh4_k, ib1, wg - NUM_I, lane);
    }
}

// ---------------------------------------------------------------------------
// Layer 2 hybrid: user gather + mean + GEMM + ReLU; item scatter -> ib2.
// ---------------------------------------------------------------------------
#define GU2 6250
#define T2  (GU2 + GS1)

__global__ void __launch_bounds__(256) combined_l2(
    const int* __restrict__ off, const float2* __restrict__ pack,
    const uint4* __restrict__ ub1v, const uint4* __restrict__ ib1v,
    __half2* __restrict__ ib2,
    const float* __restrict__ ue0f, const float* __restrict__ W,
    float* __restrict__ out, int out_stride, int out_off)
{
    __shared__ float Ws[DIM][DIM];
    int t = blockIdx.x;
    int warp = threadIdx.x >> 5, lane = threadIdx.x & 31;
    long long lo = (long long)t * GU2 / T2;
    long long hi = (long long)(t + 1) * GU2 / T2;
    if (hi > lo) {
        for (int i = threadIdx.x; i < DIM * DIM; i += blockDim.x)
            Ws[i >> 6][i & 63] = W[i];
        __syncthreads();

        const __half2* ub1 = (const __half2*)ub1v;
        const __half2* ib1 = (const __half2*)ib1v;

        for (int w = (int)lo * 8 + warp; w < NUM_U; w += GU2 * 8) {
            float ax = 0.0f, ay = 0.0f;
            seg_accum(pack, ub1, __ldg(off + BASE_A + w), __ldg(off + BASE_A + w + 1), lane, ax, ay);
            seg_accum(pack, ib1, __ldg(off + BASE_B + w), __ldg(off + BASE_B + w + 1), lane, ax, ay);

            const float inv3 = 1.0f / 3.0f;
            float2 f0 = __ldg(reinterpret_cast<const float2*>(ue0f + (size_t)w * DIM) + lane);
            float2 f1 = __half22float2(__ldg(ub1 + (size_t)w * 32 + lane));
            float m0 = (f0.x + f1.x + ax) * inv3;
            float m1 = (f0.y + f1.y + ay) * inv3;

            float acc0 = 0.0f, acc1 = 0.0f;
#pragma unroll
            for (int l = 0; l < 32; l++) {
                float b0 = __shfl_sync(0xffffffffu, m0, l);
                float b1 = __shfl_sync(0xffffffffu, m1, l);
                acc0 += b0 * Ws[2 * l][lane]      + b1 * Ws[2 * l + 1][lane];
                acc1 += b0 * Ws[2 * l][lane + 32] + b1 * Ws[2 * l + 1][lane + 32];
            }
            float* o = out + (size_t)w * out_stride + out_off;
            o[lane]      = fmaxf(acc0, 0.0f);
            o[lane + 32] = fmaxf(acc1, 0.0f);
        }
    } else {
        int wg = (t - (int)hi) * 8 + warp;
        if (wg < NUM_I)
            scatter_col(BASE_C + wg, off, pack, ib1v, ib2, wg, lane);
        else
            scatter_col(BASE_D + (wg - NUM_I), off, pack, ub1v, ib2, wg - NUM_I, lane);
    }
}

// ---------------------------------------------------------------------------
// Item combine + tail re-zero of cnt (self-cleaning graph).
// ---------------------------------------------------------------------------
__global__ void __launch_bounds__(256) item_combine(
    const float* __restrict__ ie0f,
    const __half2* __restrict__ ib1, const __half2* __restrict__ ib2,
    const float* __restrict__ W, float* __restrict__ out,
    int out_stride, int out_off, int* __restrict__ cnt_zero)
{
    __shared__ float Ws[DIM][DIM];
    for (long long i = (long long)blockIdx.x * blockDim.x + threadIdx.x;
         i < NKEYS; i += (long long)gridDim.x * blockDim.x)
        cnt_zero[i] = 0;

    for (int i = threadIdx.x; i < DIM * DIM; i += blockDim.x)
        Ws[i >> 6][i & 63] = W[i];
    __syncthreads();

    int warp = threadIdx.x >> 5, lane = threadIdx.x & 31;
    for (int w = blockIdx.x * 8 + warp; w < NUM_I; w += gridDim.x * 8) {
        const float inv3 = 1.0f / 3.0f;
        float2 f0 = __ldg(reinterpret_cast<const float2*>(ie0f + (size_t)w * DIM) + lane);
        float2 f1 = __half22float2(__ldg(ib1 + (size_t)w * 32 + lane));
        float2 f2 = __half22float2(__ldg(ib2 + (size_t)w * 32 + lane));
        float m0 = (f0.x + f1.x + f2.x) * inv3;
        float m1 = (f0.y + f1.y + f2.y) * inv3;

        float acc0 = 0.0f, acc1 = 0.0f;
#pragma unroll
        for (int l = 0; l < 32; l++) {
            float b0 = __shfl_sync(0xffffffffu, m0, l);
            float b1 = __shfl_sync(0xffffffffu, m1, l);
            acc0 += b0 * Ws[2 * l][lane]      + b1 * Ws[2 * l + 1][lane];
            acc1 += b0 * Ws[2 * l][lane + 32] + b1 * Ws[2 * l + 1][lane + 32];
        }
        float* o = out + (size_t)w * out_stride + out_off;
        o[lane]      = fmaxf(acc0, 0.0f);
        o[lane + 32] = fmaxf(acc1, 0.0f);
    }
}

// ---------------------------------------------------------------------------
extern "C" void kernel_launch(void* const* d_in, const int* in_sizes, int n_in,
                              void* d_out, int out_size)
{
    const int* u2u_r  = (const int*)d_in[0];  const int* u2u_c  = (const int*)d_in[1];
    const float* u2u_v = (const float*)d_in[2];
    const int* u2i_r0 = (const int*)d_in[3];  const int* u2i_c0 = (const int*)d_in[4];
    const float* u2i_v0 = (const float*)d_in[5];
    const int* u2i_r1 = (const int*)d_in[6];  const int* u2i_c1 = (const int*)d_in[7];
    const float* u2i_v1 = (const float*)d_in[8];
    const int* i2u_r0 = (const int*)d_in[9];  const int* i2u_c0 = (const int*)d_in[10];
    const float* i2u_v0 = (const float*)d_in[11];
    const int* i2u_r1 = (const int*)d_in[12]; const int* i2u_c1 = (const int*)d_in[13];
    const float* i2u_v1 = (const float*)d_in[14];
    const int* i2i_r  = (const int*)d_in[15]; const int* i2i_c  = (const int*)d_in[16];
    const float* i2i_v = (const float*)d_in[17];
    const float* user_embs = (const float*)d_in[18];
    const float* item_embs = (const float*)d_in[19];
    const float* W_u       = (const float*)d_in[20];
    const float* W_v       = (const float*)d_in[21];

    const int e_uu  = in_sizes[0];
    const int e_ui0 = in_sizes[3], e_ui1 = in_sizes[6];
    const int e_iu0 = in_sizes[9], e_iu1 = in_sizes[12];
    const int e_ii  = in_sizes[15];

    float* out_user = (float*)d_out;
    float* out_item = (float*)d_out + (size_t)NUM_U * (KTYP * DIM);

    uint4 *ueh4, *ieh4, *ub1v, *ib1v, *ib2v;
    float2 *pack;
    int *off, *cnt, *cur, *bs;
    cudaGetSymbolAddress((void**)&ueh4, g_ueh_v);
    cudaGetSymbolAddress((void**)&ieh4, g_ieh_v);
    cudaGetSymbolAddress((void**)&ub1v, g_ub1_v);
    cudaGetSymbolAddress((void**)&ib1v, g_ib1_v);
    cudaGetSymbolAddress((void**)&ib2v, g_ib2_v);
    cudaGetSymbolAddress((void**)&pack, g_pack);
    cudaGetSymbolAddress((void**)&off, g_off);
    cudaGetSymbolAddress((void**)&cnt, g_cnt);
    cudaGetSymbolAddress((void**)&cur, g_cur);
    cudaGetSymbolAddress((void**)&bs, g_bsums);

    // op 1: prep (convert + histogram)
    {
        long long total = (long long)KTYP * NUM_U * 32 + (long long)KTYP * NUM_I * 32
                        + e_uu + e_ui0 + e_ui1 + e_ii + e_iu0 + e_iu1;
        prep_kernel<<<(int)((total + 255) / 256), 256>>>(
            (const float2*)user_embs, (const float2*)item_embs,
            (__half2*)ueh4, (__half2*)ieh4,
            u2u_r, u2i_r0, u2i_r1, i2i_c, i2u_c0, i2u_c1,
            cnt, e_uu, e_ui0, e_ui1, e_ii, e_iu0, e_iu1);
    }

    // ops 2+3: scan
    scan_reduce<<<NB_SCAN, 1024>>>(cnt, bs);
    scan_write<<<NB_SCAN, 1024>>>(cnt, bs, off, cur);

    // op 4: scatter edges + zero ib1/ib2
    {
        long long nzero4 = (long long)KTYP * NUM_I * 8;
        long long total = (long long)e_uu + e_ui0 + e_ui1 + e_ii + e_iu0 + e_iu1
                        + 2 * nzero4;
        scatter_edges<<<(int)((total + 255) / 256), 256>>>(
            u2u_r, u2u_c, u2u_v, u2i_r0, u2i_c0, u2i_v0, u2i_r1, u2i_c1, u2i_v1,
            i2i_r, i2i_c, i2i_v, i2u_r0, i2u_c0, i2u_v0, i2u_r1, i2u_c1, i2u_v1,
            cur, pack, ib1v, ib2v, nzero4,
            e_uu, e_ui0, e_ui1, e_ii, e_iu0, e_iu1);
    }

    // main loop: type-sequential (keeps per-type working set in L2)
    for (int k = 0; k < KTYP; k++) {
        const float* ue0f = user_embs + (size_t)k * NUM_U * DIM;
        const float* ie0f = item_embs + (size_t)k * NUM_I * DIM;
        const uint4* uk4  = ueh4 + (size_t)k * NUM_U * 8;
        const uint4* ik4  = ieh4 + (size_t)k * NUM_I * 8;
        uint4* ib1k = ib1v + (size_t)k * SI4;
        uint4* ib2k = ib2v + (size_t)k * SI4;

        combined_l1<<<T1, 256>>>(off, pack, uk4, ik4,
                                 (__half2*)ub1v, (__half2*)ib1k);

        combined_l2<<<T2, 256>>>(off, pack, ub1v, ib1k, (__half2*)ib2k,
                                 ue0f, W_u + (size_t)k * DIM * DIM,
                                 out_user, KTYP * DIM, k * DIM);

        item_combine<<<3125, 256>>>(ie0f, (const __half2*)ib1k, (const __half2*)ib2k,
                                    W_v + (size_t)k * DIM * DIM,
                                    out_item, KTYP * DIM, k * DIM, cnt);
    }
}

// round 16
// speedup vs baseline: 1.0367x; 1.0015x over previous
#include <cuda_runtime.h>
#include <cuda_fp16.h>
#include <cuda_bf16.h>

#define NUM_U 200000
#define NUM_I 100000
#define DIM   64
#define KTYP  4
#define NKEYS (2*NUM_U + NUM_I + NUM_U)   // A:200K B:200K C:100K D:200K = 700K
#define NB_SCAN ((NKEYS + 1023) / 1024)   // 684
#define E_TOT 8400000

#define BASE_A 0
#define BASE_B (NUM_U)
#define BASE_C (2*NUM_U)
#define BASE_D (2*NUM_U + NUM_I)

#define SI  ((size_t)NUM_I * 32)
#define SI4 ((size_t)NUM_I * 8)

#define GU1 25000
#define GS1 37500
#define T1  (GU1 + GS1)
#define GU2 6250
#define T2  (GU2 + GS1)
#define NCMB 3125

// ---- scratch (device globals; zero-init at load; uint4 => 16B aligned) ----
__device__ uint4   g_ueh_v[(size_t)KTYP * NUM_U * 8];
__device__ uint4   g_ieh_v[(size_t)KTYP * NUM_I * 8];
__device__ uint4   g_ub1_v[(size_t)NUM_U * 8];
__device__ uint4   g_ib1_v[(size_t)KTYP * NUM_I * 8];
__device__ uint4   g_ib2_v[(size_t)KTYP * NUM_I * 8];

__device__ float2 g_pack[E_TOT];
__device__ int    g_off[NKEYS + 1];
__device__ int    g_cnt[NKEYS];      // histogram; re-zeroed at graph tail
__device__ int    g_cur[NKEYS];      // scatter cursors
__device__ int    g_bsums[NB_SCAN];

// ---------------------------------------------------------------------------
// Op 1 — prep: fp32->half2 conversion + all histograms (cnt zero on entry).
// ---------------------------------------------------------------------------
__global__ void prep_kernel(
    const float2* __restrict__ uemb, const float2* __restrict__ iemb,
    __half2* __restrict__ ueh, __half2* __restrict__ ieh,
    const int* __restrict__ u2u_r,
    const int* __restrict__ u2i_r0, const int* __restrict__ u2i_r1,
    const int* __restrict__ i2i_c,
    const int* __restrict__ i2u_c0, const int* __restrict__ i2u_c1,
    int* __restrict__ cnt,
    int e_uu, int e_ui0, int e_ui1, int e_ii, int e_iu0, int e_iu1)
{
    const long long UCNT = (long long)KTYP * NUM_U * 32;
    const long long ICNT = (long long)KTYP * NUM_I * 32;
    long long i = (long long)blockIdx.x * blockDim.x + threadIdx.x;

    if (i < UCNT) { float2 f = __ldg(uemb + i); ueh[i] = __floats2half2_rn(f.x, f.y); return; }
    i -= UCNT;
    if (i < ICNT) { float2 f = __ldg(iemb + i); ieh[i] = __floats2half2_rn(f.x, f.y); return; }
    i -= ICNT;
    if (i < e_uu)  { atomicAdd(cnt + BASE_A + __ldg(u2u_r  + i), 1); return; }
    i -= e_uu;
    if (i < e_ui0) { atomicAdd(cnt + BASE_B + __ldg(u2i_r0 + i), 1); return; }
    i -= e_ui0;
    if (i < e_ui1) { atomicAdd(cnt + BASE_B + NUM_U/2 + __ldg(u2i_r1 + i), 1); return; }
    i -= e_ui1;
    if (i < e_ii)  { atomicAdd(cnt + BASE_C + __ldg(i2i_c  + i), 1); return; }
    i -= e_ii;
    if (i < e_iu0) { atomicAdd(cnt + BASE_D + __ldg(i2u_c0 + i), 1); return; }
    i -= e_iu0;
    if (i < e_iu1) { atomicAdd(cnt + BASE_D + __ldg(i2u_c1 + i), 1); return; }
}

// ---------------------------------------------------------------------------
// Ops 2+3 — two-kernel exclusive scan (writes off + cur)
// ---------------------------------------------------------------------------
__global__ void __launch_bounds__(1024) scan_reduce(const int* __restrict__ cnt,
                                                    int* __restrict__ bsums)
{
    __shared__ int sh[1024];
    int i = blockIdx.x * 1024 + threadIdx.x;
    sh[threadIdx.x] = (i < NKEYS) ? cnt[i] : 0;
    __syncthreads();
    for (int s = 512; s > 0; s >>= 1) {
        if (threadIdx.x < s) sh[threadIdx.x] += sh[threadIdx.x + s];
        __syncthreads();
    }
    if (threadIdx.x == 0) bsums[blockIdx.x] = sh[0];
}

__global__ void __launch_bounds__(1024) scan_write(const int* __restrict__ cnt,
                                                   const int* __restrict__ bsums,
                                                   int* __restrict__ off,
                                                   int* __restrict__ cur)
{
    __shared__ int sh[1024];
    __shared__ int s_pref;
    int v = (threadIdx.x < blockIdx.x && threadIdx.x < NB_SCAN) ? bsums[threadIdx.x] : 0;
    sh[threadIdx.x] = v;
    __syncthreads();
    for (int s = 512; s > 0; s >>= 1) {
        if (threadIdx.x < s) sh[threadIdx.x] += sh[threadIdx.x + s];
        __syncthreads();
    }
    if (threadIdx.x == 0) s_pref = sh[0];
    __syncthreads();

    int i = blockIdx.x * 1024 + threadIdx.x;
    int c = (i < NKEYS) ? cnt[i] : 0;
    sh[threadIdx.x] = c;
    __syncthreads();
    for (int d = 1; d < 1024; d <<= 1) {
        int t = (threadIdx.x >= d) ? sh[threadIdx.x - d] : 0;
        __syncthreads();
        sh[threadIdx.x] += t;
        __syncthreads();
    }
    int excl = s_pref + sh[threadIdx.x] - c;
    if (i < NKEYS) { off[i] = excl; cur[i] = excl; }
    if (i == NKEYS - 1) off[NKEYS] = excl + c;
}

// ---------------------------------------------------------------------------
// Op 4 — scatter edges into compact pack; tail zeroes ib1/ib2.
// ---------------------------------------------------------------------------
__global__ void scatter_edges(
    const int* __restrict__ u2u_r, const int* __restrict__ u2u_c, const float* __restrict__ u2u_v,
    const int* __restrict__ u2i_r0, const int* __restrict__ u2i_c0, const float* __restrict__ u2i_v0,
    const int* __restrict__ u2i_r1, const int* __restrict__ u2i_c1, const float* __restrict__ u2i_v1,
    const int* __restrict__ i2i_r, const int* __restrict__ i2i_c, const float* __restrict__ i2i_v,
    const int* __restrict__ i2u_r0, const int* __restrict__ i2u_c0, const float* __restrict__ i2u_v0,
    const int* __restrict__ i2u_r1, const int* __restrict__ i2u_c1, const float* __restrict__ i2u_v1,
    int* __restrict__ cur, float2* __restrict__ pack,
    uint4* __restrict__ zb1, uint4* __restrict__ zb2, long long nzero4,
    int e_uu, int e_ui0, int e_ui1, int e_ii, int e_iu0, int e_iu1)
{
    long long i = (long long)blockIdx.x * blockDim.x + threadIdx.x;
    int key, payload; float val;
    if (i < e_uu) {
        key = BASE_A + __ldg(u2u_r + i); payload = __ldg(u2u_c + i); val = __ldg(u2u_v + i);
    } else if ((i -= e_uu) < e_ui0) {
        key = BASE_B + __ldg(u2i_r0 + i); payload = __ldg(u2i_c0 + i); val = __ldg(u2i_v0 + i);
    } else if ((i -= e_ui0) < e_ui1) {
        key = BASE_B + NUM_U/2 + __ldg(u2i_r1 + i); payload = __ldg(u2i_c1 + i); val = __ldg(u2i_v1 + i);
    } else if ((i -= e_ui1) < e_ii) {
        key = BASE_C + __ldg(i2i_c + i); payload = __ldg(i2i_r + i); val = __ldg(i2i_v + i);
    } else if ((i -= e_ii) < e_iu0) {
        key = BASE_D + __ldg(i2u_c0 + i); payload = __ldg(i2u_r0 + i); val = __ldg(i2u_v0 + i);
    } else if ((i -= e_iu0) < e_iu1) {
        key = BASE_D + __ldg(i2u_c1 + i); payload = __ldg(i2u_r1 + i) + NUM_I/2; val = __ldg(i2u_v1 + i);
    } else {
        i -= e_iu1;
        uint4 z = make_uint4(0, 0, 0, 0);
        if (i < nzero4) zb1[i] = z;
        else if ((i -= nzero4) < nzero4) zb2[i] = z;
        return;
    }
    int pos = atomicAdd(&cur[key], 1);
    pack[pos] = make_float2(__int_as_float(payload), val);
}

// ---------------------------------------------------------------------------
// Gather segment accumulate: 4-deep pipeline (default-policy loads)
// ---------------------------------------------------------------------------
__device__ __forceinline__ void seg_accum(const float2* __restrict__ pack,
                                          const __half2* __restrict__ src,
                                          int s, int e, int lane,
                                          float& ax, float& ay)
{
    int i = s;
    for (; i + 4 <= e; i += 4) {
        float2 p0 = __ldg(pack + i);
        float2 p1 = __ldg(pack + i + 1);
        float2 p2 = __ldg(pack + i + 2);
        float2 p3 = __ldg(pack + i + 3);
        float2 v0 = __half22float2(__ldg(src + (size_t)__float_as_int(p0.x) * 32 + lane));
        float2 v1 = __half22float2(__ldg(src + (size_t)__float_as_int(p1.x) * 32 + lane));
        float2 v2 = __half22float2(__ldg(src + (size_t)__float_as_int(p2.x) * 32 + lane));
        float2 v3 = __half22float2(__ldg(src + (size_t)__float_as_int(p3.x) * 32 + lane));
        ax = fmaf(p0.y, v0.x, ax); ay = fmaf(p0.y, v0.y, ay);
        ax = fmaf(p1.y, v1.x, ax); ay = fmaf(p1.y, v1.y, ay);
        ax = fmaf(p2.y, v2.x, ax); ay = fmaf(p2.y, v2.y, ay);
        ax = fmaf(p3.y, v3.x, ax); ay = fmaf(p3.y, v3.y, ay);
    }
    for (; i < e; i++) {
        float2 p = __ldg(pack + i);
        float2 v = __half22float2(__ldg(src + (size_t)__float_as_int(p.x) * 32 + lane));
        ax = fmaf(p.y, v.x, ax); ay = fmaf(p.y, v.y, ay);
    }
}

// ---------------------------------------------------------------------------
// Lean scatter (R15-proven): uint4 preload, hoisted conversions, no shfl.
// ---------------------------------------------------------------------------
__device__ __forceinline__ unsigned pk_f2(float2 f, float v)
{
    __half2 r = __floats2half2_rn(v * f.x, v * f.y);
    return *reinterpret_cast<unsigned*>(&r);
}

__device__ __forceinline__ void scatter_col(int key,
                                            const int* __restrict__ off,
                                            const float2* __restrict__ pack,
                                            const uint4* __restrict__ src4,
                                            __half2* __restrict__ dstbase,
                                            int col, int lane)
{
    int s = __ldg(off + key), e = __ldg(off + key + 1);
    if (s == e) return;
    int j  = lane & 7;
    int ei = lane >> 3;
    uint4 q = __ldg(src4 + (size_t)col * 8 + j);
    float2 f0 = __half22float2(*reinterpret_cast<__half2*>(&q.x));
    float2 f1 = __half22float2(*reinterpret_cast<__half2*>(&q.y));
    float2 f2 = __half22float2(*reinterpret_cast<__half2*>(&q.z));
    float2 f3 = __half22float2(*reinterpret_cast<__half2*>(&q.w));
    for (int i = s + ei; i < e; i += 4) {
        float2 p = __ldg(pack + i);
        int dst = __float_as_int(p.x);
        float v = p.y;
        unsigned q0 = pk_f2(f0, v), q1 = pk_f2(f1, v);
        unsigned q2 = pk_f2(f2, v), q3 = pk_f2(f3, v);
        __half2* ptr = dstbase + (size_t)dst * 32 + 4 * j;
        asm volatile("red.global.add.noftz.v4.f16x2 [%0], {%1,%2,%3,%4};"
                     :: "l"(ptr), "r"(q0), "r"(q1), "r"(q2), "r"(q3)
                     : "memory");
    }
}

// ---------------------------------------------------------------------------
// Item combine body (streaming job; Ws passed in)
// ---------------------------------------------------------------------------
__device__ __forceinline__ void comb_body(int t,
    const float* __restrict__ ie0f,
    const __half2* __restrict__ ib1, const __half2* __restrict__ ib2,
    const float* __restrict__ W, float* __restrict__ out, int out_off,
    float (*Ws)[DIM], int warp, int lane)
{
    for (int i = threadIdx.x; i < DIM * DIM; i += blockDim.x)
        Ws[i >> 6][i & 63] = W[i];
    __syncthreads();

    for (int w = t * 8 + warp; w < NUM_I; w += NCMB * 8) {
        const float inv3 = 1.0f / 3.0f;
        float2 f0 = __ldg(reinterpret_cast<const float2*>(ie0f + (size_t)w * DIM) + lane);
        float2 f1 = __half22float2(__ldg(ib1 + (size_t)w * 32 + lane));
        float2 f2 = __half22float2(__ldg(ib2 + (size_t)w * 32 + lane));
        float m0 = (f0.x + f1.x + f2.x) * inv3;
        float m1 = (f0.y + f1.y + f2.y) * inv3;

        float acc0 = 0.0f, acc1 = 0.0f;
#pragma unroll
        for (int l = 0; l < 32; l++) {
            float b0 = __shfl_sync(0xffffffffu, m0, l);
            float b1 = __shfl_sync(0xffffffffu, m1, l);
            acc0 += b0 * Ws[2 * l][lane]      + b1 * Ws[2 * l + 1][lane];
            acc1 += b0 * Ws[2 * l][lane + 32] + b1 * Ws[2 * l + 1][lane + 32];
        }
        float* o = out + (size_t)w * (KTYP * DIM) + out_off;
        o[lane]      = fmaxf(acc0, 0.0f);
        o[lane + 32] = fmaxf(acc1, 0.0f);
    }
}

// ---------------------------------------------------------------------------
// Layer 1 hybrid + folded previous-type item combine (streaming tail blocks).
// has_comb=0 on the first type.
// ---------------------------------------------------------------------------
__global__ void __launch_bounds__(256) combined_l1(
    const int* __restrict__ off, const float2* __restrict__ pack,
    const uint4* __restrict__ ueh4_k, const uint4* __restrict__ ieh4_k,
    __half2* __restrict__ ub1, __half2* __restrict__ ib1,
    // folded comb job (previous type); ignored when blockIdx.x < T1
    const float* __restrict__ ie0f_p, const __half2* __restrict__ ib1_p,
    const __half2* __restrict__ ib2_p, const float* __restrict__ W_p,
    float* __restrict__ out_item, int offi_p)
{
    __shared__ float Ws[DIM][DIM];
    int warp = threadIdx.x >> 5, lane = threadIdx.x & 31;

    if (blockIdx.x >= T1) {
        comb_body(blockIdx.x - T1, ie0f_p, ib1_p, ib2_p, W_p,
                  out_item, offi_p, Ws, warp, lane);
        return;
    }

    int t = blockIdx.x;
    long long lo = (long long)t * GU1 / T1;
    long long hi = (long long)(t + 1) * GU1 / T1;
    if (hi > lo) {
        int w = (int)lo * 8 + warp;
        float ax = 0.0f, ay = 0.0f;
        seg_accum(pack, (const __half2*)ueh4_k, __ldg(off + BASE_A + w), __ldg(off + BASE_A + w + 1), lane, ax, ay);
        seg_accum(pack, (const __half2*)ieh4_k, __ldg(off + BASE_B + w), __ldg(off + BASE_B + w + 1), lane, ax, ay);
        ub1[(size_t)w * 32 + lane] = __floats2half2_rn(ax, ay);
    } else {
        int wg = (t - (int)hi) * 8 + warp;
        if (wg < NUM_I)
            scatter_col(BASE_C + wg, off, pack, ieh4_k, ib1, wg, lane);
        else
            scatter_col(BASE_D + (wg - NUM_I), off, pack, ueh4_k, ib1, wg - NUM_I, lane);
    }
}

// ---------------------------------------------------------------------------
// Layer 2 hybrid: user gather + mean + GEMM + ReLU; item scatter -> ib2.
// ---------------------------------------------------------------------------
__global__ void __launch_bounds__(256) combined_l2(
    const int* __restrict__ off, const float2* __restrict__ pack,
    const uint4* __restrict__ ub1v, const uint4* __restrict__ ib1v,
    __half2* __restrict__ ib2,
    const float* __restrict__ ue0f, const float* __restrict__ W,
    float* __restrict__ out, int out_stride, int out_off)
{
    __shared__ float Ws[DIM][DIM];
    int t = blockIdx.x;
    int warp = threadIdx.x >> 5, lane = threadIdx.x & 31;
    long long lo = (long long)t * GU2 / T2;
    long long hi = (long long)(t + 1) * GU2 / T2;
    if (hi > lo) {
        for (int i = threadIdx.x; i < DIM * DIM; i += blockDim.x)
            Ws[i >> 6][i & 63] = W[i];
        __syncthreads();

        const __half2* ub1 = (const __half2*)ub1v;
        const __half2* ib1 = (const __half2*)ib1v;

        for (int w = (int)lo * 8 + warp; w < NUM_U; w += GU2 * 8) {
            float ax = 0.0f, ay = 0.0f;
            seg_accum(pack, ub1, __ldg(off + BASE_A + w), __ldg(off + BASE_A + w + 1), lane, ax, ay);
            seg_accum(pack, ib1, __ldg(off + BASE_B + w), __ldg(off + BASE_B + w + 1), lane, ax, ay);

            const float inv3 = 1.0f / 3.0f;
            float2 f0 = __ldg(reinterpret_cast<const float2*>(ue0f + (size_t)w * DIM) + lane);
            float2 f1 = __half22float2(__ldg(ub1 + (size_t)w * 32 + lane));
            float m0 = (f0.x + f1.x + ax) * inv3;
            float m1 = (f0.y + f1.y + ay) * inv3;

            float acc0 = 0.0f, acc1 = 0.0f;
#pragma unroll
            for (int l = 0; l < 32; l++) {
                float b0 = __shfl_sync(0xffffffffu, m0, l);
                float b1 = __shfl_sync(0xffffffffu, m1, l);
                acc0 += b0 * Ws[2 * l][lane]      + b1 * Ws[2 * l + 1][lane];
                acc1 += b0 * Ws[2 * l][lane + 32] + b1 * Ws[2 * l + 1][lane + 32];
            }
            float* o = out + (size_t)w * out_stride + out_off;
            o[lane]      = fmaxf(acc0, 0.0f);
            o[lane + 32] = fmaxf(acc1, 0.0f);
        }
    } else {
        int wg = (t - (int)hi) * 8 + warp;
        if (wg < NUM_I)
            scatter_col(BASE_C + wg, off, pack, ib1v, ib2, wg, lane);
        else
            scatter_col(BASE_D + (wg - NUM_I), off, pack, ub1v, ib2, wg - NUM_I, lane);
    }
}

// ---------------------------------------------------------------------------
// Final item combine (last type) + cnt re-zero (self-cleaning graph).
// ---------------------------------------------------------------------------
__global__ void __launch_bounds__(256) final_combine(
    const float* __restrict__ ie0f,
    const __half2* __restrict__ ib1, const __half2* __restrict__ ib2,
    const float* __restrict__ W, float* __restrict__ out, int out_off,
    int* __restrict__ cnt_zero)
{
    __shared__ float Ws[DIM][DIM];
    for (long long i = (long long)blockIdx.x * blockDim.x + threadIdx.x;
         i < NKEYS; i += (long long)gridDim.x * blockDim.x)
        cnt_zero[i] = 0;

    int warp = threadIdx.x >> 5, lane = threadIdx.x & 31;
    comb_body(blockIdx.x, ie0f, ib1, ib2, W, out, out_off, Ws, warp, lane);
}

// ---------------------------------------------------------------------------
extern "C" void kernel_launch(void* const* d_in, const int* in_sizes, int n_in,
                              void* d_out, int out_size)
{
    const int* u2u_r  = (const int*)d_in[0];  const int* u2u_c  = (const int*)d_in[1];
    const float* u2u_v = (const float*)d_in[2];
    const int* u2i_r0 = (const int*)d_in[3];  const int* u2i_c0 = (const int*)d_in[4];
    const float* u2i_v0 = (const float*)d_in[5];
    const int* u2i_r1 = (const int*)d_in[6];  const int* u2i_c1 = (const int*)d_in[7];
    const float* u2i_v1 = (const float*)d_in[8];
    const int* i2u_r0 = (const int*)d_in[9];  const int* i2u_c0 = (const int*)d_in[10];
    const float* i2u_v0 = (const float*)d_in[11];
    const int* i2u_r1 = (const int*)d_in[12]; const int* i2u_c1 = (const int*)d_in[13];
    const float* i2u_v1 = (const float*)d_in[14];
    const int* i2i_r  = (const int*)d_in[15]; const int* i2i_c  = (const int*)d_in[16];
    const float* i2i_v = (const float*)d_in[17];
    const float* user_embs = (const float*)d_in[18];
    const float* item_embs = (const float*)d_in[19];
    const float* W_u       = (const float*)d_in[20];
    const float* W_v       = (const float*)d_in[21];

    const int e_uu  = in_sizes[0];
    const int e_ui0 = in_sizes[3], e_ui1 = in_sizes[6];
    const int e_iu0 = in_sizes[9], e_iu1 = in_sizes[12];
    const int e_ii  = in_sizes[15];

    float* out_user = (float*)d_out;
    float* out_item = (float*)d_out + (size_t)NUM_U * (KTYP * DIM);

    uint4 *ueh4, *ieh4, *ub1v, *ib1v, *ib2v;
    float2 *pack;
    int *off, *cnt, *cur, *bs;
    cudaGetSymbolAddress((void**)&ueh4, g_ueh_v);
    cudaGetSymbolAddress((void**)&ieh4, g_ieh_v);
    cudaGetSymbolAddress((void**)&ub1v, g_ub1_v);
    cudaGetSymbolAddress((void**)&ib1v, g_ib1_v);
    cudaGetSymbolAddress((void**)&ib2v, g_ib2_v);
    cudaGetSymbolAddress((void**)&pack, g_pack);
    cudaGetSymbolAddress((void**)&off, g_off);
    cudaGetSymbolAddress((void**)&cnt, g_cnt);
    cudaGetSymbolAddress((void**)&cur, g_cur);
    cudaGetSymbolAddress((void**)&bs, g_bsums);

    // op 1: prep (convert + histogram)
    {
        long long total = (long long)KTYP * NUM_U * 32 + (long long)KTYP * NUM_I * 32
                        + e_uu + e_ui0 + e_ui1 + e_ii + e_iu0 + e_iu1;
        prep_kernel<<<(int)((total + 255) / 256), 256>>>(
            (const float2*)user_embs, (const float2*)item_embs,
            (__half2*)ueh4, (__half2*)ieh4,
            u2u_r, u2i_r0, u2i_r1, i2i_c, i2u_c0, i2u_c1,
            cnt, e_uu, e_ui0, e_ui1, e_ii, e_iu0, e_iu1);
    }

    // ops 2+3: scan
    scan_reduce<<<NB_SCAN, 1024>>>(cnt, bs);
    scan_write<<<NB_SCAN, 1024>>>(cnt, bs, off, cur);

    // op 4: scatter edges + zero ib1/ib2
    {
        long long nzero4 = (long long)KTYP * NUM_I * 8;
        long long total = (long long)e_uu + e_ui0 + e_ui1 + e_ii + e_iu0 + e_iu1
                        + 2 * nzero4;
        scatter_edges<<<(int)((total + 255) / 256), 256>>>(
            u2u_r, u2u_c, u2u_v, u2i_r0, u2i_c0, u2i_v0, u2i_r1, u2i_c1, u2i_v1,
            i2i_r, i2i_c, i2i_v, i2u_r0, i2u_c0, i2u_v0, i2u_r1, i2u_c1, i2u_v1,
            cur, pack, ib1v, ib2v, nzero4,
            e_uu, e_ui0, e_ui1, e_ii, e_iu0, e_iu1);
    }

    // main loop: type-sequential; comb(k-1) folded into l1(k) as tail blocks
    for (int k = 0; k < KTYP; k++) {
        const float* ue0f = user_embs + (size_t)k * NUM_U * DIM;
        const uint4* uk4  = ueh4 + (size_t)k * NUM_U * 8;
        const uint4* ik4  = ieh4 + (size_t)k * NUM_I * 8;
        uint4* ib1k = ib1v + (size_t)k * SI4;
        uint4* ib2k = ib2v + (size_t)k * SI4;

        if (k == 0) {
            combined_l1<<<T1, 256>>>(off, pack, uk4, ik4,
                                     (__half2*)ub1v, (__half2*)ib1k,
                                     nullptr, nullptr, nullptr, nullptr,
                                     nullptr, 0);
        } else {
            int kp = k - 1;
            combined_l1<<<T1 + NCMB, 256>>>(off, pack, uk4, ik4,
                (__half2*)ub1v, (__half2*)ib1k,
                item_embs + (size_t)kp * NUM_I * DIM,
                (const __half2*)(ib1v + (size_t)kp * SI4),
                (const __half2*)(ib2v + (size_t)kp * SI4),
                W_v + (size_t)kp * DIM * DIM,
                out_item, kp * DIM);
        }

        combined_l2<<<T2, 256>>>(off, pack, ub1v, ib1k, (__half2*)ib2k,
                                 ue0f, W_u + (size_t)k * DIM * DIM,
                                 out_user, KTYP * DIM, k * DIM);
    }

    // final comb (type 3) + cnt re-zero
    final_combine<<<NCMB, 256>>>(item_embs + (size_t)3 * NUM_I * DIM,
                                 (const __half2*)(ib1v + (size_t)3 * SI4),
                                 (const __half2*)(ib2v + (size_t)3 * SI4),
                                 W_v + (size_t)3 * DIM * DIM,
                                 out_item, 3 * DIM, cnt);
}

// round 17
// speedup vs baseline: 1.0442x; 1.0073x over previous
#include <cuda_runtime.h>
#include <cuda_fp16.h>
#include <cuda_bf16.h>

#define NUM_U 200000
#define NUM_I 100000
#define DIM   64
#define KTYP  4
#define NKEYS (2*NUM_U + NUM_I + NUM_U)   // A:200K B:200K C:100K D:200K = 700K
#define NB_SCAN ((NKEYS + 1023) / 1024)   // 684
#define E_TOT 8400000

#define BASE_A 0
#define BASE_B (NUM_U)
#define BASE_C (2*NUM_U)
#define BASE_D (2*NUM_U + NUM_I)

#define SI  ((size_t)NUM_I * 32)
#define SI4 ((size_t)NUM_I * 8)

#define GU1 25000
#define GS1 37500
#define T1  (GU1 + GS1)
#define GU2 6250
#define T2  (GU2 + GS1)
#define NCMB 3125

// ---- scratch (device globals; zero-init at load; uint4 => 16B aligned) ----
__device__ uint4   g_ueh_v[(size_t)KTYP * NUM_U * 8];
__device__ uint4   g_ieh_v[(size_t)KTYP * NUM_I * 8];
__device__ uint4   g_ub1_v[(size_t)NUM_U * 8];
__device__ uint4   g_ib1_v[(size_t)KTYP * NUM_I * 8];
__device__ uint4   g_ib2_v[(size_t)KTYP * NUM_I * 8];

__device__ float2 g_pack[E_TOT];
__device__ int    g_off[NKEYS + 1];
__device__ int    g_cnt[NKEYS];      // histogram; re-zeroed at graph tail
__device__ int    g_cur[NKEYS];      // scatter cursors
__device__ int    g_bsums[NB_SCAN];

// ---------------------------------------------------------------------------
// Op 1 — prep: convert + histogram, 2 independent items per thread (MLP=2).
// ---------------------------------------------------------------------------
__device__ __forceinline__ void prep_one(
    long long i,
    const float2* __restrict__ uemb, const float2* __restrict__ iemb,
    __half2* __restrict__ ueh, __half2* __restrict__ ieh,
    const int* __restrict__ u2u_r,
    const int* __restrict__ u2i_r0, const int* __restrict__ u2i_r1,
    const int* __restrict__ i2i_c,
    const int* __restrict__ i2u_c0, const int* __restrict__ i2u_c1,
    int* __restrict__ cnt,
    int e_uu, int e_ui0, int e_ui1, int e_ii, int e_iu0, int e_iu1)
{
    const long long UCNT = (long long)KTYP * NUM_U * 32;
    const long long ICNT = (long long)KTYP * NUM_I * 32;
    if (i < UCNT) { float2 f = __ldg(uemb + i); ueh[i] = __floats2half2_rn(f.x, f.y); return; }
    i -= UCNT;
    if (i < ICNT) { float2 f = __ldg(iemb + i); ieh[i] = __floats2half2_rn(f.x, f.y); return; }
    i -= ICNT;
    if (i < e_uu)  { atomicAdd(cnt + BASE_A + __ldg(u2u_r  + i), 1); return; }
    i -= e_uu;
    if (i < e_ui0) { atomicAdd(cnt + BASE_B + __ldg(u2i_r0 + i), 1); return; }
    i -= e_ui0;
    if (i < e_ui1) { atomicAdd(cnt + BASE_B + NUM_U/2 + __ldg(u2i_r1 + i), 1); return; }
    i -= e_ui1;
    if (i < e_ii)  { atomicAdd(cnt + BASE_C + __ldg(i2i_c  + i), 1); return; }
    i -= e_ii;
    if (i < e_iu0) { atomicAdd(cnt + BASE_D + __ldg(i2u_c0 + i), 1); return; }
    i -= e_iu0;
    if (i < e_iu1) { atomicAdd(cnt + BASE_D + __ldg(i2u_c1 + i), 1); return; }
}

__global__ void prep_kernel(
    const float2* __restrict__ uemb, const float2* __restrict__ iemb,
    __half2* __restrict__ ueh, __half2* __restrict__ ieh,
    const int* __restrict__ u2u_r,
    const int* __restrict__ u2i_r0, const int* __restrict__ u2i_r1,
    const int* __restrict__ i2i_c,
    const int* __restrict__ i2u_c0, const int* __restrict__ i2u_c1,
    int* __restrict__ cnt, long long total,
    int e_uu, int e_ui0, int e_ui1, int e_ii, int e_iu0, int e_iu1)
{
    long long base = 2LL * ((long long)blockIdx.x * blockDim.x + threadIdx.x);
    if (base < total)
        prep_one(base, uemb, iemb, ueh, ieh, u2u_r, u2i_r0, u2i_r1,
                 i2i_c, i2u_c0, i2u_c1, cnt,
                 e_uu, e_ui0, e_ui1, e_ii, e_iu0, e_iu1);
    if (base + 1 < total)
        prep_one(base + 1, uemb, iemb, ueh, ieh, u2u_r, u2i_r0, u2i_r1,
                 i2i_c, i2u_c0, i2u_c1, cnt,
                 e_uu, e_ui0, e_ui1, e_ii, e_iu0, e_iu1);
}

// ---------------------------------------------------------------------------
// Ops 2+3 — two-kernel exclusive scan (writes off + cur)
// ---------------------------------------------------------------------------
__global__ void __launch_bounds__(1024) scan_reduce(const int* __restrict__ cnt,
                                                    int* __restrict__ bsums)
{
    __shared__ int sh[1024];
    int i = blockIdx.x * 1024 + threadIdx.x;
    sh[threadIdx.x] = (i < NKEYS) ? cnt[i] : 0;
    __syncthreads();
    for (int s = 512; s > 0; s >>= 1) {
        if (threadIdx.x < s) sh[threadIdx.x] += sh[threadIdx.x + s];
        __syncthreads();
    }
    if (threadIdx.x == 0) bsums[blockIdx.x] = sh[0];
}

__global__ void __launch_bounds__(1024) scan_write(const int* __restrict__ cnt,
                                                   const int* __restrict__ bsums,
                                                   int* __restrict__ off,
                                                   int* __restrict__ cur)
{
    __shared__ int sh[1024];
    __shared__ int s_pref;
    int v = (threadIdx.x < blockIdx.x && threadIdx.x < NB_SCAN) ? bsums[threadIdx.x] : 0;
    sh[threadIdx.x] = v;
    __syncthreads();
    for (int s = 512; s > 0; s >>= 1) {
        if (threadIdx.x < s) sh[threadIdx.x] += sh[threadIdx.x + s];
        __syncthreads();
    }
    if (threadIdx.x == 0) s_pref = sh[0];
    __syncthreads();

    int i = blockIdx.x * 1024 + threadIdx.x;
    int c = (i < NKEYS) ? cnt[i] : 0;
    sh[threadIdx.x] = c;
    __syncthreads();
    for (int d = 1; d < 1024; d <<= 1) {
        int t = (threadIdx.x >= d) ? sh[threadIdx.x - d] : 0;
        __syncthreads();
        sh[threadIdx.x] += t;
        __syncthreads();
    }
    int excl = s_pref + sh[threadIdx.x] - c;
    if (i < NKEYS) { off[i] = excl; cur[i] = excl; }
    if (i == NKEYS - 1) off[NKEYS] = excl + c;
}

// ---------------------------------------------------------------------------
// Op 4 — scatter edges (2 per thread, interleaved atomics) + zero ib1/ib2.
// ---------------------------------------------------------------------------
__device__ __forceinline__ bool edge_fetch(
    long long i,
    const int* __restrict__ u2u_r, const int* __restrict__ u2u_c, const float* __restrict__ u2u_v,
    const int* __restrict__ u2i_r0, const int* __restrict__ u2i_c0, const float* __restrict__ u2i_v0,
    const int* __restrict__ u2i_r1, const int* __restrict__ u2i_c1, const float* __restrict__ u2i_v1,
    const int* __restrict__ i2i_r, const int* __restrict__ i2i_c, const float* __restrict__ i2i_v,
    const int* __restrict__ i2u_r0, const int* __restrict__ i2u_c0, const float* __restrict__ i2u_v0,
    const int* __restrict__ i2u_r1, const int* __restrict__ i2u_c1, const float* __restrict__ i2u_v1,
    int e_uu, int e_ui0, int e_ui1, int e_ii, int e_iu0, int e_iu1,
    int& key, int& payload, float& val)
{
    if (i < e_uu) {
        key = BASE_A + __ldg(u2u_r + i); payload = __ldg(u2u_c + i); val = __ldg(u2u_v + i); return true;
    }
    i -= e_uu;
    if (i < e_ui0) {
        key = BASE_B + __ldg(u2i_r0 + i); payload = __ldg(u2i_c0 + i); val = __ldg(u2i_v0 + i); return true;
    }
    i -= e_ui0;
    if (i < e_ui1) {
        key = BASE_B + NUM_U/2 + __ldg(u2i_r1 + i); payload = __ldg(u2i_c1 + i); val = __ldg(u2i_v1 + i); return true;
    }
    i -= e_ui1;
    if (i < e_ii) {
        key = BASE_C + __ldg(i2i_c + i); payload = __ldg(i2i_r + i); val = __ldg(i2i_v + i); return true;
    }
    i -= e_ii;
    if (i < e_iu0) {
        key = BASE_D + __ldg(i2u_c0 + i); payload = __ldg(i2u_r0 + i); val = __ldg(i2u_v0 + i); return true;
    }
    i -= e_iu0;
    if (i < e_iu1) {
        key = BASE_D + __ldg(i2u_c1 + i); payload = __ldg(i2u_r1 + i) + NUM_I/2; val = __ldg(i2u_v1 + i); return true;
    }
    return false;
}

__global__ void scatter_edges(
    const int* __restrict__ u2u_r, const int* __restrict__ u2u_c, const float* __restrict__ u2u_v,
    const int* __restrict__ u2i_r0, const int* __restrict__ u2i_c0, const float* __restrict__ u2i_v0,
    const int* __restrict__ u2i_r1, const int* __restrict__ u2i_c1, const float* __restrict__ u2i_v1,
    const int* __restrict__ i2i_r, const int* __restrict__ i2i_c, const float* __restrict__ i2i_v,
    const int* __restrict__ i2u_r0, const int* __restrict__ i2u_c0, const float* __restrict__ i2u_v0,
    const int* __restrict__ i2u_r1, const int* __restrict__ i2u_c1, const float* __restrict__ i2u_v1,
    int* __restrict__ cur, float2* __restrict__ pack,
    uint4* __restrict__ zb1, uint4* __restrict__ zb2, long long nzero4,
    long long e_total,
    int e_uu, int e_ui0, int e_ui1, int e_ii, int e_iu0, int e_iu1)
{
    long long base = 2LL * ((long long)blockIdx.x * blockDim.x + threadIdx.x);

    if (base < e_total) {
        // two independent edges: fetch both, issue both atomics, then stores
        int k0, p0, k1 = -1, p1 = 0;
        float v0, v1 = 0.0f;
        edge_fetch(base, u2u_r, u2u_c, u2u_v, u2i_r0, u2i_c0, u2i_v0,
                   u2i_r1, u2i_c1, u2i_v1, i2i_r, i2i_c, i2i_v,
                   i2u_r0, i2u_c0, i2u_v0, i2u_r1, i2u_c1, i2u_v1,
                   e_uu, e_ui0, e_ui1, e_ii, e_iu0, e_iu1, k0, p0, v0);
        bool has1 = (base + 1 < e_total) &&
            edge_fetch(base + 1, u2u_r, u2u_c, u2u_v, u2i_r0, u2i_c0, u2i_v0,
                       u2i_r1, u2i_c1, u2i_v1, i2i_r, i2i_c, i2i_v,
                       i2u_r0, i2u_c0, i2u_v0, i2u_r1, i2u_c1, i2u_v1,
                       e_uu, e_ui0, e_ui1, e_ii, e_iu0, e_iu1, k1, p1, v1);
        int pos0 = atomicAdd(&cur[k0], 1);
        int pos1 = has1 ? atomicAdd(&cur[k1], 1) : 0;
        pack[pos0] = make_float2(__int_as_float(p0), v0);
        if (has1) pack[pos1] = make_float2(__int_as_float(p1), v1);
        return;
    }

    // zero-fill tail region (2 uint4 per thread)
    long long z = base - e_total;
    uint4 zero = make_uint4(0, 0, 0, 0);
    if (z < nzero4) zb1[z] = zero;
    else if (z - nzero4 < nzero4) zb2[z - nzero4] = zero;
    long long z1 = z + 1;
    if (z1 >= 0) {
        if (z1 < nzero4) zb1[z1] = zero;
        else if (z1 - nzero4 < nzero4) zb2[z1 - nzero4] = zero;
    }
}

// ---------------------------------------------------------------------------
// Gather segment accumulate: 4-deep pipeline
// ---------------------------------------------------------------------------
__device__ __forceinline__ void seg_accum(const float2* __restrict__ pack,
                                          const __half2* __restrict__ src,
                                          int s, int e, int lane,
                                          float& ax, float& ay)
{
    int i = s;
    for (; i + 4 <= e; i += 4) {
        float2 p0 = __ldg(pack + i);
        float2 p1 = __ldg(pack + i + 1);
        float2 p2 = __ldg(pack + i + 2);
        float2 p3 = __ldg(pack + i + 3);
        float2 v0 = __half22float2(__ldg(src + (size_t)__float_as_int(p0.x) * 32 + lane));
        float2 v1 = __half22float2(__ldg(src + (size_t)__float_as_int(p1.x) * 32 + lane));
        float2 v2 = __half22float2(__ldg(src + (size_t)__float_as_int(p2.x) * 32 + lane));
        float2 v3 = __half22float2(__ldg(src + (size_t)__float_as_int(p3.x) * 32 + lane));
        ax = fmaf(p0.y, v0.x, ax); ay = fmaf(p0.y, v0.y, ay);
        ax = fmaf(p1.y, v1.x, ax); ay = fmaf(p1.y, v1.y, ay);
        ax = fmaf(p2.y, v2.x, ax); ay = fmaf(p2.y, v2.y, ay);
        ax = fmaf(p3.y, v3.x, ax); ay = fmaf(p3.y, v3.y, ay);
    }
    for (; i < e; i++) {
        float2 p = __ldg(pack + i);
        float2 v = __half22float2(__ldg(src + (size_t)__float_as_int(p.x) * 32 + lane));
        ax = fmaf(p.y, v.x, ax); ay = fmaf(p.y, v.y, ay);
    }
}

// ---------------------------------------------------------------------------
// Lean scatter with 2-deep pack pipeline (reds are fire-and-forget).
// ---------------------------------------------------------------------------
__device__ __forceinline__ unsigned pk_f2(float2 f, float v)
{
    __half2 r = __floats2half2_rn(v * f.x, v * f.y);
    return *reinterpret_cast<unsigned*>(&r);
}

__device__ __forceinline__ void scatter_col(int key,
                                            const int* __restrict__ off,
                                            const float2* __restrict__ pack,
                                            const uint4* __restrict__ src4,
                                            __half2* __restrict__ dstbase,
                                            int col, int lane)
{
    int s = __ldg(off + key), e = __ldg(off + key + 1);
    if (s == e) return;
    int j  = lane & 7;
    int ei = lane >> 3;
    uint4 q = __ldg(src4 + (size_t)col * 8 + j);
    float2 f0 = __half22float2(*reinterpret_cast<__half2*>(&q.x));
    float2 f1 = __half22float2(*reinterpret_cast<__half2*>(&q.y));
    float2 f2 = __half22float2(*reinterpret_cast<__half2*>(&q.z));
    float2 f3 = __half22float2(*reinterpret_cast<__half2*>(&q.w));
    __half2* db = dstbase + 4 * j;

    int i = s + ei;
    for (; i + 4 < e; i += 8) {
        float2 pa = __ldg(pack + i);
        float2 pb = __ldg(pack + i + 4);
        {
            float v = pa.y;
            __half2* ptr = db + (size_t)__float_as_int(pa.x) * 32;
            asm volatile("red.global.add.noftz.v4.f16x2 [%0], {%1,%2,%3,%4};"
                         :: "l"(ptr), "r"(pk_f2(f0, v)), "r"(pk_f2(f1, v)),
                            "r"(pk_f2(f2, v)), "r"(pk_f2(f3, v)) : "memory");
        }
        {
            float v = pb.y;
            __half2* ptr = db + (size_t)__float_as_int(pb.x) * 32;
            asm volatile("red.global.add.noftz.v4.f16x2 [%0], {%1,%2,%3,%4};"
                         :: "l"(ptr), "r"(pk_f2(f0, v)), "r"(pk_f2(f1, v)),
                            "r"(pk_f2(f2, v)), "r"(pk_f2(f3, v)) : "memory");
        }
    }
    if (i < e) {
        float2 p = __ldg(pack + i);
        float v = p.y;
        __half2* ptr = db + (size_t)__float_as_int(p.x) * 32;
        asm volatile("red.global.add.noftz.v4.f16x2 [%0], {%1,%2,%3,%4};"
                     :: "l"(ptr), "r"(pk_f2(f0, v)), "r"(pk_f2(f1, v)),
                        "r"(pk_f2(f2, v)), "r"(pk_f2(f3, v)) : "memory");
    }
}

// ---------------------------------------------------------------------------
// Item combine body (streaming job)
// ---------------------------------------------------------------------------
__device__ __forceinline__ void comb_body(int t,
    const float* __restrict__ ie0f,
    const __half2* __restrict__ ib1, const __half2* __restrict__ ib2,
    const float* __restrict__ W, float* __restrict__ out, int out_off,
    float (*Ws)[DIM], int warp, int lane)
{
    for (int i = threadIdx.x; i < DIM * DIM; i += blockDim.x)
        Ws[i >> 6][i & 63] = W[i];
    __syncthreads();

    for (int w = t * 8 + warp; w < NUM_I; w += NCMB * 8) {
        const float inv3 = 1.0f / 3.0f;
        float2 f0 = __ldg(reinterpret_cast<const float2*>(ie0f + (size_t)w * DIM) + lane);
        float2 f1 = __half22float2(__ldg(ib1 + (size_t)w * 32 + lane));
        float2 f2 = __half22float2(__ldg(ib2 + (size_t)w * 32 + lane));
        float m0 = (f0.x + f1.x + f2.x) * inv3;
        float m1 = (f0.y + f1.y + f2.y) * inv3;

        float acc0 = 0.0f, acc1 = 0.0f;
#pragma unroll
        for (int l = 0; l < 32; l++) {
            float b0 = __shfl_sync(0xffffffffu, m0, l);
            float b1 = __shfl_sync(0xffffffffu, m1, l);
            acc0 += b0 * Ws[2 * l][lane]      + b1 * Ws[2 * l + 1][lane];
            acc1 += b0 * Ws[2 * l][lane + 32] + b1 * Ws[2 * l + 1][lane + 32];
        }
        float* o = out + (size_t)w * (KTYP * DIM) + out_off;
        o[lane]      = fmaxf(acc0, 0.0f);
        o[lane + 32] = fmaxf(acc1, 0.0f);
    }
}

// ---------------------------------------------------------------------------
// Layer 1 hybrid + folded previous-type item combine
// ---------------------------------------------------------------------------
__global__ void __launch_bounds__(256) combined_l1(
    const int* __restrict__ off, const float2* __restrict__ pack,
    const uint4* __restrict__ ueh4_k, const uint4* __restrict__ ieh4_k,
    __half2* __restrict__ ub1, __half2* __restrict__ ib1,
    const float* __restrict__ ie0f_p, const __half2* __restrict__ ib1_p,
    const __half2* __restrict__ ib2_p, const float* __restrict__ W_p,
    float* __restrict__ out_item, int offi_p)
{
    __shared__ float Ws[DIM][DIM];
    int warp = threadIdx.x >> 5, lane = threadIdx.x & 31;

    if (blockIdx.x >= T1) {
        comb_body(blockIdx.x - T1, ie0f_p, ib1_p, ib2_p, W_p,
                  out_item, offi_p, Ws, warp, lane);
        return;
    }

    int t = blockIdx.x;
    long long lo = (long long)t * GU1 / T1;
    long long hi = (long long)(t + 1) * GU1 / T1;
    if (hi > lo) {
        int w = (int)lo * 8 + warp;
        float ax = 0.0f, ay = 0.0f;
        seg_accum(pack, (const __half2*)ueh4_k, __ldg(off + BASE_A + w), __ldg(off + BASE_A + w + 1), lane, ax, ay);
        seg_accum(pack, (const __half2*)ieh4_k, __ldg(off + BASE_B + w), __ldg(off + BASE_B + w + 1), lane, ax, ay);
        ub1[(size_t)w * 32 + lane] = __floats2half2_rn(ax, ay);
    } else {
        int wg = (t - (int)hi) * 8 + warp;
        if (wg < NUM_I)
            scatter_col(BASE_C + wg, off, pack, ieh4_k, ib1, wg, lane);
        else
            scatter_col(BASE_D + (wg - NUM_I), off, pack, ueh4_k, ib1, wg - NUM_I, lane);
    }
}

// ---------------------------------------------------------------------------
// Layer 2 hybrid: user gather + mean + GEMM + ReLU; item scatter -> ib2.
// ---------------------------------------------------------------------------
__global__ void __launch_bounds__(256) combined_l2(
    const int* __restrict__ off, const float2* __restrict__ pack,
    const uint4* __restrict__ ub1v, const uint4* __restrict__ ib1v,
    __half2* __restrict__ ib2,
    const float* __restrict__ ue0f, const float* __restrict__ W,
    float* __restrict__ out, int out_stride, int out_off)
{
    __shared__ float Ws[DIM][DIM];
    int t = blockIdx.x;
    int warp = threadIdx.x >> 5, lane = threadIdx.x & 31;
    long long lo = (long long)t * GU2 / T2;
    long long hi = (long long)(t + 1) * GU2 / T2;
    if (hi > lo) {
        for (int i = threadIdx.x; i < DIM * DIM; i += blockDim.x)
            Ws[i >> 6][i & 63] = W[i];
        __syncthreads();

        const __half2* ub1 = (const __half2*)ub1v;
        const __half2* ib1 = (const __half2*)ib1v;

        for (int w = (int)lo * 8 + warp; w < NUM_U; w += GU2 * 8) {
            float ax = 0.0f, ay = 0.0f;
            seg_accum(pack, ub1, __ldg(off + BASE_A + w), __ldg(off + BASE_A + w + 1), lane, ax, ay);
            seg_accum(pack, ib1, __ldg(off + BASE_B + w), __ldg(off + BASE_B + w + 1), lane, ax, ay);

            const float inv3 = 1.0f / 3.0f;
            float2 f0 = __ldg(reinterpret_cast<const float2*>(ue0f + (size_t)w * DIM) + lane);
            float2 f1 = __half22float2(__ldg(ub1 + (size_t)w * 32 + lane));
            float m0 = (f0.x + f1.x + ax) * inv3;
            float m1 = (f0.y + f1.y + ay) * inv3;

            float acc0 = 0.0f, acc1 = 0.0f;
#pragma unroll
            for (int l = 0; l < 32; l++) {
                float b0 = __shfl_sync(0xffffffffu, m0, l);
                float b1 = __shfl_sync(0xffffffffu, m1, l);
                acc0 += b0 * Ws[2 * l][lane]      + b1 * Ws[2 * l + 1][lane];
                acc1 += b0 * Ws[2 * l][lane + 32] + b1 * Ws[2 * l + 1][lane + 32];
            }
            float* o = out + (size_t)w * out_stride + out_off;
            o[lane]      = fmaxf(acc0, 0.0f);
            o[lane + 32] = fmaxf(acc1, 0.0f);
        }
    } else {
        int wg = (t - (int)hi) * 8 + warp;
        if (wg < NUM_I)
            scatter_col(BASE_C + wg, off, pack, ib1v, ib2, wg, lane);
        else
            scatter_col(BASE_D + (wg - NUM_I), off, pack, ub1v, ib2, wg - NUM_I, lane);
    }
}

// ---------------------------------------------------------------------------
// Final item combine (last type) + cnt re-zero (self-cleaning graph).
// ---------------------------------------------------------------------------
__global__ void __launch_bounds__(256) final_combine(
    const float* __restrict__ ie0f,
    const __half2* __restrict__ ib1, const __half2* __restrict__ ib2,
    const float* __restrict__ W, float* __restrict__ out, int out_off,
    int* __restrict__ cnt_zero)
{
    __shared__ float Ws[DIM][DIM];
    for (long long i = (long long)blockIdx.x * blockDim.x + threadIdx.x;
         i < NKEYS; i += (long long)gridDim.x * blockDim.x)
        cnt_zero[i] = 0;

    int warp = threadIdx.x >> 5, lane = threadIdx.x & 31;
    comb_body(blockIdx.x, ie0f, ib1, ib2, W, out, out_off, Ws, warp, lane);
}

// ---------------------------------------------------------------------------
extern "C" void kernel_launch(void* const* d_in, const int* in_sizes, int n_in,
                              void* d_out, int out_size)
{
    const int* u2u_r  = (const int*)d_in[0];  const int* u2u_c  = (const int*)d_in[1];
    const float* u2u_v = (const float*)d_in[2];
    const int* u2i_r0 = (const int*)d_in[3];  const int* u2i_c0 = (const int*)d_in[4];
    const float* u2i_v0 = (const float*)d_in[5];
    const int* u2i_r1 = (const int*)d_in[6];  const int* u2i_c1 = (const int*)d_in[7];
    const float* u2i_v1 = (const float*)d_in[8];
    const int* i2u_r0 = (const int*)d_in[9];  const int* i2u_c0 = (const int*)d_in[10];
    const float* i2u_v0 = (const float*)d_in[11];
    const int* i2u_r1 = (const int*)d_in[12]; const int* i2u_c1 = (const int*)d_in[13];
    const float* i2u_v1 = (const float*)d_in[14];
    const int* i2i_r  = (const int*)d_in[15]; const int* i2i_c  = (const int*)d_in[16];
    const float* i2i_v = (const float*)d_in[17];
    const float* user_embs = (const float*)d_in[18];
    const float* item_embs = (const float*)d_in[19];
    const float* W_u       = (const float*)d_in[20];
    const float* W_v       = (const float*)d_in[21];

    const int e_uu  = in_sizes[0];
    const int e_ui0 = in_sizes[3], e_ui1 = in_sizes[6];
    const int e_iu0 = in_sizes[9], e_iu1 = in_sizes[12];
    const int e_ii  = in_sizes[15];

    float* out_user = (float*)d_out;
    float* out_item = (float*)d_out + (size_t)NUM_U * (KTYP * DIM);

    uint4 *ueh4, *ieh4, *ub1v, *ib1v, *ib2v;
    float2 *pack;
    int *off, *cnt, *cur, *bs;
    cudaGetSymbolAddress((void**)&ueh4, g_ueh_v);
    cudaGetSymbolAddress((void**)&ieh4, g_ieh_v);
    cudaGetSymbolAddress((void**)&ub1v, g_ub1_v);
    cudaGetSymbolAddress((void**)&ib1v, g_ib1_v);
    cudaGetSymbolAddress((void**)&ib2v, g_ib2_v);
    cudaGetSymbolAddress((void**)&pack, g_pack);
    cudaGetSymbolAddress((void**)&off, g_off);
    cudaGetSymbolAddress((void**)&cnt, g_cnt);
    cudaGetSymbolAddress((void**)&cur, g_cur);
    cudaGetSymbolAddress((void**)&bs, g_bsums);

    // op 1: prep (convert + histogram), 2 items/thread
    {
        long long total = (long long)KTYP * NUM_U * 32 + (long long)KTYP * NUM_I * 32
                        + e_uu + e_ui0 + e_ui1 + e_ii + e_iu0 + e_iu1;
        long long threads = (total + 1) / 2;
        prep_kernel<<<(int)((threads + 255) / 256), 256>>>(
            (const float2*)user_embs, (const float2*)item_embs,
            (__half2*)ueh4, (__half2*)ieh4,
            u2u_r, u2i_r0, u2i_r1, i2i_c, i2u_c0, i2u_c1,
            cnt, total, e_uu, e_ui0, e_ui1, e_ii, e_iu0, e_iu1);
    }

    // ops 2+3: scan
    scan_reduce<<<NB_SCAN, 1024>>>(cnt, bs);
    scan_write<<<NB_SCAN, 1024>>>(cnt, bs, off, cur);

    // op 4: scatter edges (2/thread) + zero ib1/ib2
    {
        long long e_total = (long long)e_uu + e_ui0 + e_ui1 + e_ii + e_iu0 + e_iu1;
        long long nzero4 = (long long)KTYP * NUM_I * 8;
        long long total = e_total + 2 * nzero4;
        long long threads = (total + 1) / 2;
        scatter_edges<<<(int)((threads + 255) / 256), 256>>>(
            u2u_r, u2u_c, u2u_v, u2i_r0, u2i_c0, u2i_v0, u2i_r1, u2i_c1, u2i_v1,
            i2i_r, i2i_c, i2i_v, i2u_r0, i2u_c0, i2u_v0, i2u_r1, i2u_c1, i2u_v1,
            cur, pack, ib1v, ib2v, nzero4, e_total,
            e_uu, e_ui0, e_ui1, e_ii, e_iu0, e_iu1);
    }

    // main loop: type-sequential; comb(k-1) folded into l1(k)
    for (int k = 0; k < KTYP; k++) {
        const float* ue0f = user_embs + (size_t)k * NUM_U * DIM;
        const uint4* uk4  = ueh4 + (size_t)k * NUM_U * 8;
        const uint4* ik4  = ieh4 + (size_t)k * NUM_I * 8;
        uint4* ib1k = ib1v + (size_t)k * SI4;
        uint4* ib2k = ib2v + (size_t)k * SI4;

        if (k == 0) {
            combined_l1<<<T1, 256>>>(off, pack, uk4, ik4,
                                     (__half2*)ub1v, (__half2*)ib1k,
                                     nullptr, nullptr, nullptr, nullptr,
                                     nullptr, 0);
        } else {
            int kp = k - 1;
            combined_l1<<<T1 + NCMB, 256>>>(off, pack, uk4, ik4,
                (__half2*)ub1v, (__half2*)ib1k,
                item_embs + (size_t)kp * NUM_I * DIM,
                (const __half2*)(ib1v + (size_t)kp * SI4),
                (const __half2*)(ib2v + (size_t)kp * SI4),
                W_v + (size_t)kp * DIM * DIM,
                out_item, kp * DIM);
        }

        combined_l2<<<T2, 256>>>(off, pack, ub1v, ib1k, (__half2*)ib2k,
                                 ue0f, W_u + (size_t)k * DIM * DIM,
                                 out_user, KTYP * DIM, k * DIM);
    }

    // final comb (type 3) + cnt re-zero
    final_combine<<<NCMB, 256>>>(item_embs + (size_t)3 * NUM_I * DIM,
                                 (const __half2*)(ib1v + (size_t)3 * SI4),
                                 (const __half2*)(ib2v + (size_t)3 * SI4),
                                 W_v + (size_t)3 * DIM * DIM,
                                 out_item, 3 * DIM, cnt);
}